// round 11
// baseline (speedup 1.0000x reference)
#include <cuda_runtime.h>
#include <cuda_bf16.h>
#include <math.h>

#define Bn 2
#define Ln 2048
#define Kn 32
#define NF 128
#define FSTR 404   // feats row stride in floats (16B-aligned rows: 404*4=1616)

#define HV_OFF   0
#define HE_OFF   (Bn*Ln*NF)                        // 524288
#define EIDX_OFF (HE_OFF + Bn*Ln*Kn*NF)            // 17301504
#define X_OFF    (EIDX_OFF + Bn*Ln*Kn)             // 17432576

__device__ int g_eidx[Bn*Ln*Kn];

typedef unsigned long long u64;

// ---------- packed f32x2 helpers (sm_10x) ----------
__device__ __forceinline__ u64 dup2(float v){ u64 r; asm("mov.b64 %0, {%1, %1};" : "=l"(r) : "f"(v)); return r; }
__device__ __forceinline__ u64 fma2(u64 a, u64 b, u64 c){ u64 d; asm("fma.rn.f32x2 %0, %1, %2, %3;" : "=l"(d) : "l"(a), "l"(b), "l"(c)); return d; }
__device__ __forceinline__ u64 add2(u64 a, u64 b){ u64 d; asm("add.rn.f32x2 %0, %1, %2;" : "=l"(d) : "l"(a), "l"(b)); return d; }
__device__ __forceinline__ void unpack2(u64 v, float& lo, float& hi){ asm("mov.b64 {%0, %1}, %2;" : "=f"(lo), "=f"(hi) : "l"(v)); }

// ---------- XLA:GPU exact chain ----------
struct V3 { float x,y,z; };
__device__ __forceinline__ V3 vsub(V3 a, V3 b){
  V3 r; r.x=__fsub_rn(a.x,b.x); r.y=__fsub_rn(a.y,b.y); r.z=__fsub_rn(a.z,b.z); return r;
}
// fsub(fmul,fmul) contraction: fma(ay,bz, -(az*by))  [== nvcc r1 == 1-flip chain]
__device__ __forceinline__ V3 cross_x(V3 a, V3 b){
  V3 r;
  r.x = __fmaf_rn(a.y, b.z, -__fmul_rn(a.z, b.y));
  r.y = __fmaf_rn(a.z, b.x, -__fmul_rn(a.x, b.z));
  r.z = __fmaf_rn(a.x, b.y, -__fmul_rn(a.y, b.x));
  return r;
}
// ((m0+m1)+m2) contracted: fma(z,z2, fma(x,x2, mul(y,y2)))
__device__ __forceinline__ float dot_x(V3 a, V3 b){
  return __fmaf_rn(a.z, b.z, __fmaf_rn(a.x, b.x, __fmul_rn(a.y, b.y)));
}
__device__ __forceinline__ float n2n(float x){
  if (isnan(x)) return 0.0f;
  if (isinf(x)) return copysignf(3.402823466e38f, x);
  return x;
}
// XLA:GPU f32 divide lowers to div.full.f32 (full-range approximate, <=2ulp),
// not div.rn — this is the reference's extra noise source (fp64-truth itself
// disagrees with the reference at 2-3 borderline-acos edges).
__device__ __forceinline__ float div_full(float a, float b){
  float r; asm("div.full.f32 %0, %1, %2;" : "=f"(r) : "f"(a), "f"(b)); return r;
}
__device__ __forceinline__ V3 norm_x(V3 v){
  float n = __fsqrt_rn(dot_x(v,v));
  V3 r;
  r.x = n2n(div_full(v.x, n));
  r.y = n2n(div_full(v.y, n));
  r.z = n2n(div_full(v.z, n));
  return r;
}
// acos: NaN set is {|x|>1} for every lowering (verified r5==r7); boundary is
// decided purely by the bits of x. Keep the XLA expansion form.
__device__ __forceinline__ float acos_xla(float x){
  if (x == -1.0f) return 3.14159265358979323846f;
  float t = __fmaf_rn(-x, x, 1.0f);
  float s = __fsqrt_rn(t);                          // NaN if t < 0
  return __fmul_rn(2.0f, atan2f(s, __fadd_rn(1.0f, x)));
}
__device__ __forceinline__ float dihedral(V3 p0, V3 p1, V3 p2, V3 p3){
  V3 u0=vsub(p2,p1), u1=vsub(p0,p1), u2=vsub(p3,p2);
  V3 a=norm_x(cross_x(u0,u1));
  V3 b=norm_x(cross_x(u0,u2));
  float st = dot_x(cross_x(u1,u2), u0);
  float sgn = (st>0.f)?1.f:((st<0.f)?-1.f:0.f);
  float r = __fmul_rn(sgn, acos_xla(dot_x(a,b)));
  if (isnan(r)) r = 0.f;               // nan_to_num
  return r;
}

// Cb = -0.58273431*cross(Ca-N, C-Ca) + 0.56802827*(Ca-N) - 0.54067466*(C-Ca) + Ca
// (feeds only the continuous RBF path; contraction-level rounding is fine)
__device__ __forceinline__ void comp_cb(const float* p, float* cb){
  float bx=p[3]-p[0], by=p[4]-p[1], bz=p[5]-p[2];
  float cx=p[6]-p[3], cy=p[7]-p[4], cz=p[8]-p[5];
  float ax = by*cz - bz*cy, ay = bz*cx - bx*cz, az = bx*cy - by*cx;
  cb[0] = -0.58273431f*ax + 0.56802827f*bx - 0.54067466f*cx + p[3];
  cb[1] = -0.58273431f*ay + 0.56802827f*by - 0.54067466f*cy + p[4];
  cb[2] = -0.58273431f*az + 0.56802827f*bz - 0.54067466f*cz + p[5];
}

// =====================================================================
// Kernel 1: masked distances + top-K (stable, lowest-index tie-break)
// one block per (b,i); also copies X row and writes E_idx as float
// =====================================================================
__global__ void __launch_bounds__(256) knn_kernel(
    const float* __restrict__ X, const float* __restrict__ mask,
    float* __restrict__ out)
{
  __shared__ float Dv[Ln];
  __shared__ float Mv[Ln];
  __shared__ float fred[8];
  __shared__ u64 ured[8];

  int tid = threadIdx.x;
  int g = blockIdx.x;              // b*Ln + i
  int b = g >> 11;
  int i = g & (Ln-1);
  const float* Xb = X + (size_t)b*Ln*12;
  float cax = Xb[(size_t)i*12+3], cay = Xb[(size_t)i*12+4], caz = Xb[(size_t)i*12+5];
  float mi = mask[g];

  float lmax = 0.0f;
  for (int j = tid; j < Ln; j += 256){
    float dx = __fsub_rn(cax, Xb[(size_t)j*12+3]);
    float dy = __fsub_rn(cay, Xb[(size_t)j*12+4]);
    float dz = __fsub_rn(caz, Xb[(size_t)j*12+5]);
    float m2 = __fmul_rn(mi, mask[b*Ln + j]);
    float ss = __fadd_rn(
        __fmaf_rn(dz, dz, __fmaf_rn(dx, dx, __fmul_rn(dy, dy))), 1e-6f);
    float D = __fmul_rn(m2, __fsqrt_rn(ss));
    Dv[j] = D; Mv[j] = m2;
    lmax = fmaxf(lmax, D);
  }
  #pragma unroll
  for (int o=16;o;o>>=1) lmax = fmaxf(lmax, __shfl_xor_sync(0xffffffffu, lmax, o));
  if ((tid&31)==0) fred[tid>>5] = lmax;
  __syncthreads();
  float Dmax = fred[0];
  #pragma unroll
  for (int q=1;q<8;q++) Dmax = fmaxf(Dmax, fred[q]);
  // D_adj = D + 2*(1-m2)*rowmax(D)   (== D exactly when m2==1)
  for (int j = tid; j < Ln; j += 256)
    Dv[j] = __fadd_rn(Dv[j],
            __fmul_rn(__fmul_rn(2.0f, __fsub_rn(1.0f, Mv[j])), Dmax));
  __syncthreads();

  int base = g*Kn;
  for (int k=0;k<Kn;k++){
    u64 best = ~0ull;
    for (int j = tid; j < Ln; j += 256){
      u64 key = ((u64)__float_as_uint(Dv[j]) << 32) | (unsigned)j;
      best = (key < best) ? key : best;
    }
    #pragma unroll
    for (int o=16;o;o>>=1){
      u64 other = __shfl_xor_sync(0xffffffffu, best, o);
      best = (other < best) ? other : best;
    }
    if ((tid&31)==0) ured[tid>>5] = best;
    __syncthreads();
    u64 w = ured[0];
    #pragma unroll
    for (int q=1;q<8;q++) w = (ured[q] < w) ? ured[q] : w;
    int bj = (int)(w & 0xffffffffull);
    if (tid==0){
      g_eidx[base+k] = bj;
      out[EIDX_OFF + base + k] = (float)bj;
      Dv[bj] = __int_as_float(0x7f800000);  // +inf, never re-selected
    }
    __syncthreads();
  }
  // copy X row (reference returns input X)
  if (tid < 12) out[X_OFF + (size_t)g*12 + tid] = Xb[(size_t)i*12 + tid];
}

// =====================================================================
// Kernel 2: node features -> GEMM (one-hot collapsed to row lookup) -> LN
// one block (128 threads) per node
// =====================================================================
__global__ void __launch_bounds__(128) node_kernel(
    const int* __restrict__ S, const float* __restrict__ BB, const float* __restrict__ SC,
    const float* __restrict__ Wn, const float* __restrict__ bn,
    const float* __restrict__ gn, const float* __restrict__ betan,
    float* __restrict__ out)
{
  __shared__ float sv[14];
  __shared__ float red1[4];
  __shared__ float red2[4];
  int g = blockIdx.x;
  int f = threadIdx.x;
  if (f < 6) sv[f] = BB[g*6 + f];
  else if (f < 14) sv[f] = SC[g*8 + (f-6)];
  __syncthreads();
  int s = S[g];
  float h = bn[f] + Wn[s*NF + f];
  #pragma unroll
  for (int j=0;j<6;j++)  h = fmaf(sv[j],   Wn[(21+j)*NF + f], h);
  #pragma unroll
  for (int j=0;j<8;j++)  h = fmaf(sv[6+j], Wn[(27+j)*NF + f], h);

  int lane = f & 31, wid = f >> 5;
  float t = h;
  #pragma unroll
  for (int o=16;o;o>>=1) t += __shfl_xor_sync(0xffffffffu, t, o);
  if (lane==0) red1[wid] = t;
  __syncthreads();
  float mean = (red1[0]+red1[1]+red1[2]+red1[3]) * (1.0f/128.0f);
  float d = h - mean;
  float t2 = d*d;
  #pragma unroll
  for (int o=16;o;o>>=1) t2 += __shfl_xor_sync(0xffffffffu, t2, o);
  if (lane==0) red2[wid] = t2;
  __syncthreads();
  float var = (red2[0]+red2[1]+red2[2]+red2[3]) * (1.0f/128.0f);
  out[HV_OFF + (size_t)g*NF + f] = d / sqrtf(var + 1e-5f) * gn[f] + betan[f];
}

// =====================================================================
// Kernel 3: edge features + 403-wide GEMM (packed f32x2) + LN
// one block per 2 nodes (64 edges); warp handles 8 edges
// =====================================================================
__global__ void __launch_bounds__(256) edge_kernel(
    const float* __restrict__ X, const int* __restrict__ chain,
    const float* __restrict__ We, const float* __restrict__ be,
    const float* __restrict__ ge, const float* __restrict__ betae,
    float* __restrict__ out)
{
  extern __shared__ float sm[];
  float* feats = sm;                         // [64][FSTR]
  float* x5i   = sm + 64*FSTR;               // [2][15]
  int*   pos   = (int*)(sm + 64*FSTR + 32);  // [64]

  int tid = threadIdx.x;
  int g0 = blockIdx.x * 2;                   // first global node (same batch: Ln even)
  int b = g0 >> 11;

  if (tid < 24){
    int ln = tid / 12, c = tid % 12;
    x5i[ln*15 + c] = X[(size_t)(g0+ln)*12 + c];
  }
  __syncthreads();
  if (tid < 2) comp_cb(x5i + tid*15, x5i + tid*15 + 12);
  __syncthreads();

  // ---------- Phase A: per-edge features ----------
  {
    int e   = tid >> 2;        // 0..63
    int sub = tid & 3;
    int ln  = e >> 5;
    int k   = e & 31;
    int gi  = g0 + ln;
    int i   = gi & (Ln-1);
    int j   = g_eidx[gi*Kn + k];
    const float* Xb = X + (size_t)b*Ln*12;

    float n5[15];
    #pragma unroll
    for (int c=0;c<12;c++) n5[c] = Xb[(size_t)j*12 + c];
    comp_cb(n5, n5+12);

    float* F = feats + e*FSTR;
    const float* P = x5i + ln*15;
    for (int p25 = sub; p25 < 25; p25 += 4){
      int a = p25/5, q = p25%5;
      float dx = P[a*3+0]-n5[q*3+0];
      float dy = P[a*3+1]-n5[q*3+1];
      float dz = P[a*3+2]-n5[q*3+2];
      float d = sqrtf(dx*dx + dy*dy + dz*dz + 1e-6f);
      #pragma unroll
      for (int r=0;r<16;r++){
        float mu = (float)r * (20.0f/15.0f);
        float t = (d - mu) * 0.8f;           // /sigma, sigma=1.25
        F[p25*16 + r] = __expf(-t*t);
      }
    }
    if (sub == 0){
      float et = (chain[b*Ln + j] == chain[gi]) ? 2.0f : 1.0f;
      F[400] = et;
      V3 Ni  = {P[0],P[1],P[2]},  Cai = {P[3],P[4],P[5]},  Ci = {P[6],P[7],P[8]};
      V3 Nj  = {n5[0],n5[1],n5[2]}, Caj = {n5[3],n5[4],n5[5]}, Cj = {n5[6],n5[7],n5[8]};
      F[401] = dihedral(Ci, Nj, Caj, Cj);    // ir_phi
      F[402] = dihedral(Ni, Cai, Ci, Nj);    // ir_psi
      F[403] = 0.0f;
      int off = j - i + 32;
      pos[e] = min(max(off, 0), 64);
    }
  }
  __syncthreads();

  // ---------- Phase B: GEMM (rows 65..467 dense; one-hot = row lookup) ----------
  int warp = tid >> 5, lane = tid & 31;
  const u64* W2 = (const u64*)We;            // row r: W2[r*64 + c], c=0..63 (f=2c,2c+1)
  const u64* B2 = (const u64*)be;

  u64 acc[8][2];
  #pragma unroll
  for (int eo=0;eo<8;eo++){
    int ee = warp*8 + eo;
    int pr = pos[ee];
    acc[eo][0] = add2(B2[lane],      W2[pr*64 + lane]);
    acc[eo][1] = add2(B2[lane+32],   W2[pr*64 + lane + 32]);
  }
  for (int r=0;r<400;r+=4){
    u64 wa[4], wb[4];
    #pragma unroll
    for (int q=0;q<4;q++){
      wa[q] = W2[(65+r+q)*64 + lane];
      wb[q] = W2[(65+r+q)*64 + lane + 32];
    }
    #pragma unroll
    for (int eo=0;eo<8;eo++){
      const float4 ev = *(const float4*)(feats + (warp*8+eo)*FSTR + r);
      u64 e0=dup2(ev.x), e1=dup2(ev.y), e2=dup2(ev.z), e3=dup2(ev.w);
      acc[eo][0]=fma2(e0,wa[0],acc[eo][0]); acc[eo][1]=fma2(e0,wb[0],acc[eo][1]);
      acc[eo][0]=fma2(e1,wa[1],acc[eo][0]); acc[eo][1]=fma2(e1,wb[1],acc[eo][1]);
      acc[eo][0]=fma2(e2,wa[2],acc[eo][0]); acc[eo][1]=fma2(e2,wb[2],acc[eo][1]);
      acc[eo][0]=fma2(e3,wa[3],acc[eo][0]); acc[eo][1]=fma2(e3,wb[3],acc[eo][1]);
    }
  }
  #pragma unroll
  for (int r=400;r<403;r++){
    u64 wa = W2[(65+r)*64 + lane], wb = W2[(65+r)*64 + lane + 32];
    #pragma unroll
    for (int eo=0;eo<8;eo++){
      u64 ev = dup2(feats[(warp*8+eo)*FSTR + r]);
      acc[eo][0]=fma2(ev,wa,acc[eo][0]); acc[eo][1]=fma2(ev,wb,acc[eo][1]);
    }
  }

  // ---------- LN + store (each edge lives in one warp) ----------
  float2 gg0 = ((const float2*)ge)[lane];
  float2 gg1 = ((const float2*)ge)[lane+32];
  float2 bb0 = ((const float2*)betae)[lane];
  float2 bb1 = ((const float2*)betae)[lane+32];
  #pragma unroll
  for (int eo=0;eo<8;eo++){
    float v0,v1,v2,v3;
    unpack2(acc[eo][0], v0, v1);
    unpack2(acc[eo][1], v2, v3);
    float s = v0+v1+v2+v3;
    #pragma unroll
    for (int o=16;o;o>>=1) s += __shfl_xor_sync(0xffffffffu, s, o);
    float mean = s * (1.0f/128.0f);
    float d0=v0-mean, d1=v1-mean, d2=v2-mean, d3=v3-mean;
    float s2 = d0*d0 + d1*d1 + d2*d2 + d3*d3;
    #pragma unroll
    for (int o=16;o;o>>=1) s2 += __shfl_xor_sync(0xffffffffu, s2, o);
    float var = s2 * (1.0f/128.0f);
    float inv = 1.0f / sqrtf(var + 1e-5f);

    int ee = warp*8 + eo;
    int ln2 = ee >> 5, k2 = ee & 31;
    size_t eg = (size_t)(g0 + ln2)*Kn + k2;
    float2* O2 = (float2*)(out + HE_OFF + eg*NF);
    float2 r0, r1;
    r0.x = d0*inv*gg0.x + bb0.x;  r0.y = d1*inv*gg0.y + bb0.y;
    r1.x = d2*inv*gg1.x + bb1.x;  r1.y = d3*inv*gg1.y + bb1.y;
    O2[lane]      = r0;
    O2[lane + 32] = r1;
  }
}

#define EDGE_SMEM ((64*FSTR + 32)*4 + 64*4)

extern "C" void kernel_launch(void* const* d_in, const int* in_sizes, int n_in,
                              void* d_out, int out_size) {
  (void)in_sizes; (void)n_in; (void)out_size;
  const float* X     = (const float*)d_in[0];
  const int*   S     = (const int*)  d_in[1];
  const float* BB    = (const float*)d_in[2];
  const float* SC    = (const float*)d_in[3];
  const int*   chain = (const int*)  d_in[4];
  const float* mask  = (const float*)d_in[5];
  const float* Wn    = (const float*)d_in[6];
  const float* bn    = (const float*)d_in[7];
  const float* gn    = (const float*)d_in[8];
  const float* betan = (const float*)d_in[9];
  const float* We    = (const float*)d_in[10];
  const float* be    = (const float*)d_in[11];
  const float* ge    = (const float*)d_in[12];
  const float* betae = (const float*)d_in[13];
  float* out = (float*)d_out;

  cudaFuncSetAttribute(edge_kernel, cudaFuncAttributeMaxDynamicSharedMemorySize, EDGE_SMEM);

  knn_kernel <<<Bn*Ln, 256>>>(X, mask, out);
  node_kernel<<<Bn*Ln, 128>>>(S, BB, SC, Wn, bn, gn, betan, out);
  edge_kernel<<<Bn*Ln/2, 256, EDGE_SMEM>>>(X, chain, We, be, ge, betae, out);
}

// round 13
// speedup vs baseline: 1.3107x; 1.3107x over previous
#include <cuda_runtime.h>
#include <cuda_fp16.h>
#include <math.h>

#define Bn 2
#define Ln 2048
#define Kn 32
#define NF 128

#define HV_OFF   0
#define HE_OFF   (Bn*Ln*NF)                        // 524288
#define EIDX_OFF (HE_OFF + Bn*Ln*Kn*NF)            // 17301504
#define X_OFF    (EIDX_OFF + Bn*Ln*Kn)             // 17432576

// GEMM: 64 edges (2 nodes) per block, K 403 -> 448 (7 chunks of 64 fp16)
#define NCHUNK 7
#define ACH 8192                 // A chunk: 64 rows x 128B
#define BCH 16384                // B chunk: 128 rows x 128B

__device__ int g_eidx[Bn*Ln*Kn];
__device__ __align__(16) unsigned char g_Bhalf[NCHUNK*BCH];  // W fp16, SW128 chunk image

typedef unsigned long long u64;

#define SWZ(o) ((o) ^ (((o) >> 3) & 0x70))

// ---------- r11-exact math chain (div.full.f32 normalize — passing config) ----------
struct V3 { float x,y,z; };
__device__ __forceinline__ V3 vsub(V3 a, V3 b){
  V3 r; r.x=__fsub_rn(a.x,b.x); r.y=__fsub_rn(a.y,b.y); r.z=__fsub_rn(a.z,b.z); return r;
}
__device__ __forceinline__ V3 cross_x(V3 a, V3 b){
  V3 r;
  r.x = __fmaf_rn(a.y, b.z, -__fmul_rn(a.z, b.y));
  r.y = __fmaf_rn(a.z, b.x, -__fmul_rn(a.x, b.z));
  r.z = __fmaf_rn(a.x, b.y, -__fmul_rn(a.y, b.x));
  return r;
}
__device__ __forceinline__ float dot_x(V3 a, V3 b){
  return __fmaf_rn(a.z, b.z, __fmaf_rn(a.x, b.x, __fmul_rn(a.y, b.y)));
}
__device__ __forceinline__ float n2n(float x){
  if (isnan(x)) return 0.0f;
  if (isinf(x)) return copysignf(3.402823466e38f, x);
  return x;
}
__device__ __forceinline__ float div_full(float a, float b){
  float r; asm("div.full.f32 %0, %1, %2;" : "=f"(r) : "f"(a), "f"(b)); return r;
}
__device__ __forceinline__ V3 norm_x(V3 v){
  float n = __fsqrt_rn(dot_x(v,v));
  V3 r;
  r.x = n2n(div_full(v.x, n));
  r.y = n2n(div_full(v.y, n));
  r.z = n2n(div_full(v.z, n));
  return r;
}
__device__ __forceinline__ float acos_xla(float x){
  if (x == -1.0f) return 3.14159265358979323846f;
  float t = __fmaf_rn(-x, x, 1.0f);
  float s = __fsqrt_rn(t);
  return __fmul_rn(2.0f, atan2f(s, __fadd_rn(1.0f, x)));
}
__device__ __forceinline__ float dihedral(V3 p0, V3 p1, V3 p2, V3 p3){
  V3 u0=vsub(p2,p1), u1=vsub(p0,p1), u2=vsub(p3,p2);
  V3 a=norm_x(cross_x(u0,u1));
  V3 b=norm_x(cross_x(u0,u2));
  float st = dot_x(cross_x(u1,u2), u0);
  float sgn = (st>0.f)?1.f:((st<0.f)?-1.f:0.f);
  float r = __fmul_rn(sgn, acos_xla(dot_x(a,b)));
  if (isnan(r)) r = 0.f;
  return r;
}
__device__ __forceinline__ void comp_cb(const float* p, float* cb){
  float bx=p[3]-p[0], by=p[4]-p[1], bz=p[5]-p[2];
  float cx=p[6]-p[3], cy=p[7]-p[4], cz=p[8]-p[5];
  float ax = by*cz - bz*cy, ay = bz*cx - bx*cz, az = bx*cy - by*cx;
  cb[0] = -0.58273431f*ax + 0.56802827f*bx - 0.54067466f*cx + p[3];
  cb[1] = -0.58273431f*ay + 0.56802827f*by - 0.54067466f*cy + p[4];
  cb[2] = -0.58273431f*az + 0.56802827f*bz - 0.54067466f*cz + p[5];
}
__device__ __forceinline__ unsigned smem_u32(const void* p){
  unsigned a;
  asm("{ .reg .u64 t; cvta.to.shared.u64 t, %1; cvt.u32.u64 %0, t; }" : "=r"(a) : "l"(p));
  return a;
}

// =====================================================================
// Kernel 0: W_edge rows 65..467 -> fp16 SW128-chunk image (B[n][k] = W[65+k][n])
// =====================================================================
__global__ void wconv_kernel(const float* __restrict__ We){
  int idx = blockIdx.x*256 + threadIdx.x;           // 7*128*64 = 57344
  if (idx >= NCHUNK*128*64) return;
  int c  = idx / (128*64);
  int r  = idx % (128*64);
  int n  = r >> 6;
  int kk = r & 63;
  int kg = c*64 + kk;
  float v = (kg < 403) ? We[(65+kg)*NF + n] : 0.0f;
  unsigned off = ((unsigned)(n>>3)*1024) | ((unsigned)(n&7)*128) | (unsigned)(kk*2);
  *(__half*)(g_Bhalf + c*BCH + SWZ(off)) = __float2half_rn(v);
}

// =====================================================================
// Kernel 1: masked distances + register-resident two-stage top-K
// =====================================================================
__global__ void __launch_bounds__(256) knn_kernel(
    const float* __restrict__ X, const float* __restrict__ mask,
    float* __restrict__ out)
{
  __shared__ float Dv[Ln];
  __shared__ float Mv[Ln];
  __shared__ float fred[8];
  __shared__ u64 wtop[8*32];

  int tid = threadIdx.x;
  int g = blockIdx.x;
  int b = g >> 11;
  int i = g & (Ln-1);
  const float* Xb = X + (size_t)b*Ln*12;
  float cax = Xb[(size_t)i*12+3], cay = Xb[(size_t)i*12+4], caz = Xb[(size_t)i*12+5];
  float mi = mask[g];

  float lmax = 0.0f;
  for (int j = tid; j < Ln; j += 256){
    float dx = __fsub_rn(cax, Xb[(size_t)j*12+3]);
    float dy = __fsub_rn(cay, Xb[(size_t)j*12+4]);
    float dz = __fsub_rn(caz, Xb[(size_t)j*12+5]);
    float m2 = __fmul_rn(mi, mask[b*Ln + j]);
    float ss = __fadd_rn(
        __fmaf_rn(dz, dz, __fmaf_rn(dx, dx, __fmul_rn(dy, dy))), 1e-6f);
    float D = __fmul_rn(m2, __fsqrt_rn(ss));
    Dv[j] = D; Mv[j] = m2;
    lmax = fmaxf(lmax, D);
  }
  #pragma unroll
  for (int o=16;o;o>>=1) lmax = fmaxf(lmax, __shfl_xor_sync(0xffffffffu, lmax, o));
  if ((tid&31)==0) fred[tid>>5] = lmax;
  __syncthreads();
  float Dmax = fred[0];
  #pragma unroll
  for (int q=1;q<8;q++) Dmax = fmaxf(Dmax, fred[q]);
  for (int j = tid; j < Ln; j += 256)
    Dv[j] = __fadd_rn(Dv[j],
            __fmul_rn(__fmul_rn(2.0f, __fsub_rn(1.0f, Mv[j])), Dmax));
  __syncthreads();

  // Stage A: per-warp top-32 over registers (lane owns 8 contiguous j)
  int w = tid >> 5, lane = tid & 31;
  u64 key[8];
  #pragma unroll
  for (int q=0;q<8;q++){
    int j = tid*8 + q;
    key[q] = ((u64)__float_as_uint(Dv[j]) << 32) | (unsigned)j;
  }
  for (int k=0;k<Kn;k++){
    u64 m = key[0];
    #pragma unroll
    for (int q=1;q<8;q++) m = (key[q] < m) ? key[q] : m;
    #pragma unroll
    for (int o=16;o;o>>=1){
      u64 other = __shfl_xor_sync(0xffffffffu, m, o);
      m = (other < m) ? other : m;
    }
    #pragma unroll
    for (int q=0;q<8;q++) if (key[q] == m) key[q] = ~0ull;
    if (lane==0) wtop[w*32 + k] = m;
  }
  __syncthreads();

  // Stage B: warp 0 merges 8x32 candidates
  if (w == 0){
    u64 cnd[8];
    #pragma unroll
    for (int q=0;q<8;q++) cnd[q] = wtop[lane*8 + q];
    int base = g*Kn;
    for (int k=0;k<Kn;k++){
      u64 m = cnd[0];
      #pragma unroll
      for (int q=1;q<8;q++) m = (cnd[q] < m) ? cnd[q] : m;
      #pragma unroll
      for (int o=16;o;o>>=1){
        u64 other = __shfl_xor_sync(0xffffffffu, m, o);
        m = (other < m) ? other : m;
      }
      #pragma unroll
      for (int q=0;q<8;q++) if (cnd[q] == m) cnd[q] = ~0ull;
      if (lane==0){
        int bj = (int)(m & 0xffffffffull);
        g_eidx[base+k] = bj;
        out[EIDX_OFF + base + k] = (float)bj;
      }
    }
  }
  if (tid < 12) out[X_OFF + (size_t)g*12 + tid] = Xb[(size_t)i*12 + tid];
}

// =====================================================================
// Kernel 2: node features -> row-lookup GEMM -> LN (unchanged)
// =====================================================================
__global__ void __launch_bounds__(128) node_kernel(
    const int* __restrict__ S, const float* __restrict__ BB, const float* __restrict__ SC,
    const float* __restrict__ Wn, const float* __restrict__ bn,
    const float* __restrict__ gn, const float* __restrict__ betan,
    float* __restrict__ out)
{
  __shared__ float sv[14];
  __shared__ float red1[4];
  __shared__ float red2[4];
  int g = blockIdx.x;
  int f = threadIdx.x;
  if (f < 6) sv[f] = BB[g*6 + f];
  else if (f < 14) sv[f] = SC[g*8 + (f-6)];
  __syncthreads();
  int s = S[g];
  float h = bn[f] + Wn[s*NF + f];
  #pragma unroll
  for (int j=0;j<6;j++)  h = fmaf(sv[j],   Wn[(21+j)*NF + f], h);
  #pragma unroll
  for (int j=0;j<8;j++)  h = fmaf(sv[6+j], Wn[(27+j)*NF + f], h);

  int lane = f & 31, wid = f >> 5;
  float t = h;
  #pragma unroll
  for (int o=16;o;o>>=1) t += __shfl_xor_sync(0xffffffffu, t, o);
  if (lane==0) red1[wid] = t;
  __syncthreads();
  float mean = (red1[0]+red1[1]+red1[2]+red1[3]) * (1.0f/128.0f);
  float d = h - mean;
  float t2 = d*d;
  #pragma unroll
  for (int o=16;o;o>>=1) t2 += __shfl_xor_sync(0xffffffffu, t2, o);
  if (lane==0) red2[wid] = t2;
  __syncthreads();
  float var = (red2[0]+red2[1]+red2[2]+red2[3]) * (1.0f/128.0f);
  out[HV_OFF + (size_t)g*NF + f] = d / sqrtf(var + 1e-5f) * gn[f] + betan[f];
}

// =====================================================================
// Kernel 3: edge features -> fp16 A chunks + HMMA (mma.sync) + LN
// Block: 2 nodes = 64 edges, 256 threads (4/edge), 8 warps.
// smem: [0..1024) misc | A: 7 x 8KB | B: 7 x 16KB   (169KB total)
// =====================================================================
#define SM_X5I   64         // 2*15 floats
#define SM_POS   320        // 64 ints
#define SM_A     1024
#define SM_B     (SM_A + NCHUNK*ACH)               // 58368
#define EDGE_SMEM (SM_B + NCHUNK*BCH)              // 173056
#define CSTRIDE  132

__global__ void __launch_bounds__(256) edge_kernel(
    const float* __restrict__ X, const int* __restrict__ chain,
    const float* __restrict__ We, const float* __restrict__ be,
    const float* __restrict__ ge, const float* __restrict__ betae,
    float* __restrict__ out)
{
  extern __shared__ char sm[];
  unsigned smb = smem_u32(sm);
  float* x5i = (float*)(sm + SM_X5I);
  int*   pos = (int*)(sm + SM_POS);

  int tid = threadIdx.x;
  int wid = tid >> 5, lane = tid & 31;
  int g0 = blockIdx.x * 2;
  int b  = g0 >> 11;

  if (tid < 24){
    int nl = tid / 12, c = tid % 12;
    x5i[nl*15 + c] = X[(size_t)(g0+nl)*12 + c];
  }
  __syncthreads();
  if (tid < 2) comp_cb(x5i + tid*15, x5i + tid*15 + 12);
  __syncthreads();

  // ---------- Phase A: features -> fp16 SW128 A chunks ----------
  {
    int e   = tid >> 2;        // edge 0..63
    int sub = tid & 3;
    int nl  = e >> 5;
    int k   = e & 31;
    int gi  = g0 + nl;
    int i   = gi & (Ln-1);
    int j   = g_eidx[gi*Kn + k];
    const float* Xb = X + (size_t)b*Ln*12;

    float n5[15];
    #pragma unroll
    for (int c=0;c<12;c++) n5[c] = Xb[(size_t)j*12 + c];
    comp_cb(n5, n5+12);
    const float* P = x5i + nl*15;
    unsigned rowatom = (unsigned)(e>>3)*1024;
    unsigned rin     = (unsigned)(e&7)*128;

    for (int p = sub; p < 25; p += 4){
      int a = p/5, q = p%5;
      float dx = P[a*3+0]-n5[q*3+0];
      float dy = P[a*3+1]-n5[q*3+1];
      float dz = P[a*3+2]-n5[q*3+2];
      float d = sqrtf(dx*dx + dy*dy + dz*dz + 1e-6f);
      unsigned h2[8];
      #pragma unroll
      for (int r2=0;r2<8;r2++){
        float mu0 = (float)(2*r2)   * (20.0f/15.0f);
        float mu1 = (float)(2*r2+1) * (20.0f/15.0f);
        float t0 = (d - mu0) * 0.8f;
        float t1 = (d - mu1) * 0.8f;
        __half2 hh = __floats2half2_rn(__expf(-t0*t0), __expf(-t1*t1));
        h2[r2] = *(unsigned*)&hh;
      }
      int c = p >> 2;
      unsigned kb = (unsigned)(p&3)*32;
      char* base = sm + SM_A + c*ACH + rowatom;
      *(uint4*)(base + SWZ(rin + kb))      = make_uint4(h2[0],h2[1],h2[2],h2[3]);
      *(uint4*)(base + SWZ(rin + kb + 16)) = make_uint4(h2[4],h2[5],h2[6],h2[7]);
    }
    if (sub == 1){
      float et = (chain[b*Ln + j] == chain[gi]) ? 2.0f : 1.0f;
      V3 Ni  = {P[0],P[1],P[2]},  Cai = {P[3],P[4],P[5]},  Ci = {P[6],P[7],P[8]};
      V3 Nj  = {n5[0],n5[1],n5[2]}, Caj = {n5[3],n5[4],n5[5]}, Cj = {n5[6],n5[7],n5[8]};
      float d0 = dihedral(Ci, Nj, Caj, Cj);
      float d1 = dihedral(Ni, Cai, Ci, Nj);
      // chunk 6 bytes 32..127 (k = 400..447): [et, d0, d1, 0, 0...]
      __half2 hh0 = __floats2half2_rn(et, d0);
      __half2 hh1 = __floats2half2_rn(d1, 0.f);
      char* base = sm + SM_A + 6*ACH + rowatom;
      *(uint4*)(base + SWZ(rin + 32)) = make_uint4(*(unsigned*)&hh0, *(unsigned*)&hh1, 0u, 0u);
      #pragma unroll
      for (int s4=1;s4<6;s4++)
        *(uint4*)(base + SWZ(rin + 32 + (unsigned)s4*16)) = make_uint4(0u,0u,0u,0u);
      int offp = j - i + 32;
      pos[e] = min(max(offp, 0), 64);
    }
  }
  // ---------- Load full B (7 chunks, 112KB) ----------
  {
    const uint4* src = (const uint4*)g_Bhalf;
    uint4* dst = (uint4*)(sm + SM_B);
    for (int it = tid; it < NCHUNK*BCH/16; it += 256)
      dst[it] = src[it];
  }
  __syncthreads();

  // ---------- HMMA: warp w -> rows (w&1)*32..+31, cols (w>>1)*32..+31 ----------
  int mr0 = (wid & 1) * 32;
  int nc0 = (wid >> 1) * 32;
  float acc[2][4][4];
  #pragma unroll
  for (int mt=0;mt<2;mt++)
    #pragma unroll
    for (int nt=0;nt<4;nt++)
      #pragma unroll
      for (int q=0;q<4;q++) acc[mt][nt][q] = 0.f;

  for (int c = 0; c < NCHUNK; c++){
    unsigned CA = smb + SM_A + c*ACH;
    unsigned CB = smb + SM_B + c*BCH;
    #pragma unroll
    for (int ks = 0; ks < 4; ks++){
      unsigned kb = (unsigned)ks*32;
      unsigned af[2][4];
      #pragma unroll
      for (int mt=0;mt<2;mt++){
        int r = mr0 + mt*16 + (lane & 15);
        unsigned sel = (unsigned)(lane >> 4) * 16;
        unsigned addr = CA + (unsigned)(r>>3)*1024 + SWZ((unsigned)(r&7)*128 + kb + sel);
        asm volatile("ldmatrix.sync.aligned.m8n8.x4.shared.b16 {%0,%1,%2,%3}, [%4];"
          : "=r"(af[mt][0]), "=r"(af[mt][1]), "=r"(af[mt][2]), "=r"(af[mt][3]) : "r"(addr));
      }
      unsigned bf[4][2];
      #pragma unroll
      for (int nt=0;nt<4;nt++){
        int lm = lane & 15;
        int n = nc0 + nt*8 + (lm & 7);
        unsigned sel = (unsigned)((lm >> 3) & 1) * 16;
        unsigned addr = CB + (unsigned)(n>>3)*1024 + SWZ((unsigned)(n&7)*128 + kb + sel);
        asm volatile("ldmatrix.sync.aligned.m8n8.x2.shared.b16 {%0,%1}, [%2];"
          : "=r"(bf[nt][0]), "=r"(bf[nt][1]) : "r"(addr));
      }
      #pragma unroll
      for (int mt=0;mt<2;mt++)
        #pragma unroll
        for (int nt=0;nt<4;nt++)
          asm volatile(
            "mma.sync.aligned.m16n8k16.row.col.f32.f16.f16.f32 "
            "{%0,%1,%2,%3}, {%4,%5,%6,%7}, {%8,%9}, {%0,%1,%2,%3};"
            : "+f"(acc[mt][nt][0]), "+f"(acc[mt][nt][1]),
              "+f"(acc[mt][nt][2]), "+f"(acc[mt][nt][3])
            : "r"(af[mt][0]), "r"(af[mt][1]), "r"(af[mt][2]), "r"(af[mt][3]),
              "r"(bf[nt][0]), "r"(bf[nt][1]));
    }
  }
  __syncthreads();                 // all warps done reading A -> reuse as C

  // ---------- D -> smem C [64][CSTRIDE] ----------
  {
    float* C = (float*)(sm + SM_A);
    #pragma unroll
    for (int mt=0;mt<2;mt++)
      #pragma unroll
      for (int nt=0;nt<4;nt++){
        int row = mr0 + mt*16 + (lane >> 2);
        int col = nc0 + nt*8 + 2*(lane & 3);
        C[row*CSTRIDE + col]       = acc[mt][nt][0];
        C[row*CSTRIDE + col + 1]   = acc[mt][nt][1];
        C[(row+8)*CSTRIDE + col]   = acc[mt][nt][2];
        C[(row+8)*CSTRIDE + col+1] = acc[mt][nt][3];
      }
  }
  __syncthreads();

  // ---------- Epilogue: bias + one-hot row (fp32 exact) + LN ----------
  {
    const float* C = (const float*)(sm + SM_A);
    int row = tid >> 2, seg = tid & 3;
    const float* Wrow = We + (size_t)pos[row]*NF;
    float y[32];
    float sum = 0.f, sumsq = 0.f;
    #pragma unroll
    for (int q=0;q<32;q++){
      int f = seg*32 + q;
      float v = C[row*CSTRIDE + f] + be[f] + Wrow[f];
      y[q] = v; sum += v; sumsq += v*v;
    }
    sum   += __shfl_xor_sync(0xffffffffu, sum, 1);
    sum   += __shfl_xor_sync(0xffffffffu, sum, 2);
    sumsq += __shfl_xor_sync(0xffffffffu, sumsq, 1);
    sumsq += __shfl_xor_sync(0xffffffffu, sumsq, 2);
    float mean = sum * (1.0f/128.0f);
    float var  = sumsq * (1.0f/128.0f) - mean*mean;
    float inv  = 1.0f / sqrtf(var + 1e-5f);

    int nl = row >> 5, k2 = row & 31;
    float* O = out + HE_OFF + ((size_t)(g0+nl)*Kn + k2)*NF + seg*32;
    #pragma unroll
    for (int q=0;q<32;q+=4){
      int f = seg*32 + q;
      float4 o4;
      o4.x = (y[q]   - mean)*inv*ge[f]   + betae[f];
      o4.y = (y[q+1] - mean)*inv*ge[f+1] + betae[f+1];
      o4.z = (y[q+2] - mean)*inv*ge[f+2] + betae[f+2];
      o4.w = (y[q+3] - mean)*inv*ge[f+3] + betae[f+3];
      *(float4*)(O + q) = o4;
    }
  }
}

extern "C" void kernel_launch(void* const* d_in, const int* in_sizes, int n_in,
                              void* d_out, int out_size) {
  (void)in_sizes; (void)n_in; (void)out_size;
  const float* X     = (const float*)d_in[0];
  const int*   S     = (const int*)  d_in[1];
  const float* BB    = (const float*)d_in[2];
  const float* SC    = (const float*)d_in[3];
  const int*   chain = (const int*)  d_in[4];
  const float* mask  = (const float*)d_in[5];
  const float* Wn    = (const float*)d_in[6];
  const float* bn    = (const float*)d_in[7];
  const float* gn    = (const float*)d_in[8];
  const float* betan = (const float*)d_in[9];
  const float* We    = (const float*)d_in[10];
  const float* be    = (const float*)d_in[11];
  const float* ge    = (const float*)d_in[12];
  const float* betae = (const float*)d_in[13];
  float* out = (float*)d_out;

  cudaFuncSetAttribute(edge_kernel, cudaFuncAttributeMaxDynamicSharedMemorySize, EDGE_SMEM);

  wconv_kernel<<<(NCHUNK*128*64 + 255)/256, 256>>>(We);
  knn_kernel  <<<Bn*Ln, 256>>>(X, mask, out);
  node_kernel <<<Bn*Ln, 128>>>(S, BB, SC, Wn, bn, gn, betan, out);
  edge_kernel <<<Bn*Ln/2, 256, EDGE_SMEM>>>(X, chain, We, be, ge, betae, out);
}

// round 14
// speedup vs baseline: 1.4795x; 1.1288x over previous
#include <cuda_runtime.h>
#include <cuda_fp16.h>
#include <math.h>

#define Bn 2
#define Ln 2048
#define Kn 32
#define NF 128

#define HV_OFF   0
#define HE_OFF   (Bn*Ln*NF)                        // 524288
#define EIDX_OFF (HE_OFF + Bn*Ln*Kn*NF)            // 17301504
#define X_OFF    (EIDX_OFF + Bn*Ln*Kn)             // 17432576

// GEMM: 64 edges (2 nodes) per block, K 403 -> 448 (7 chunks of 64 fp16)
#define NCHUNK 7
#define ACH 8192                 // A chunk: 64 rows x 128B
#define BCH 16384                // B chunk: 128 rows x 128B

__device__ int g_eidx[Bn*Ln*Kn];
__device__ __align__(16) unsigned char g_Bhalf[NCHUNK*BCH];  // W fp16, SW128 chunk image
__device__ __align__(16) float4 g_ca[Bn*Ln];                 // packed (Ca.xyz, mask)

typedef unsigned long long u64;

#define SWZ(o) ((o) ^ (((o) >> 3) & 0x70))

// ---------- r11-exact math chain (div.full.f32 normalize — passing config) ----------
struct V3 { float x,y,z; };
__device__ __forceinline__ V3 vsub(V3 a, V3 b){
  V3 r; r.x=__fsub_rn(a.x,b.x); r.y=__fsub_rn(a.y,b.y); r.z=__fsub_rn(a.z,b.z); return r;
}
__device__ __forceinline__ V3 cross_x(V3 a, V3 b){
  V3 r;
  r.x = __fmaf_rn(a.y, b.z, -__fmul_rn(a.z, b.y));
  r.y = __fmaf_rn(a.z, b.x, -__fmul_rn(a.x, b.z));
  r.z = __fmaf_rn(a.x, b.y, -__fmul_rn(a.y, b.x));
  return r;
}
__device__ __forceinline__ float dot_x(V3 a, V3 b){
  return __fmaf_rn(a.z, b.z, __fmaf_rn(a.x, b.x, __fmul_rn(a.y, b.y)));
}
__device__ __forceinline__ float n2n(float x){
  if (isnan(x)) return 0.0f;
  if (isinf(x)) return copysignf(3.402823466e38f, x);
  return x;
}
__device__ __forceinline__ float div_full(float a, float b){
  float r; asm("div.full.f32 %0, %1, %2;" : "=f"(r) : "f"(a), "f"(b)); return r;
}
__device__ __forceinline__ V3 norm_x(V3 v){
  float n = __fsqrt_rn(dot_x(v,v));
  V3 r;
  r.x = n2n(div_full(v.x, n));
  r.y = n2n(div_full(v.y, n));
  r.z = n2n(div_full(v.z, n));
  return r;
}
__device__ __forceinline__ float acos_xla(float x){
  if (x == -1.0f) return 3.14159265358979323846f;
  float t = __fmaf_rn(-x, x, 1.0f);
  float s = __fsqrt_rn(t);
  return __fmul_rn(2.0f, atan2f(s, __fadd_rn(1.0f, x)));
}
__device__ __forceinline__ float dihedral(V3 p0, V3 p1, V3 p2, V3 p3){
  V3 u0=vsub(p2,p1), u1=vsub(p0,p1), u2=vsub(p3,p2);
  V3 a=norm_x(cross_x(u0,u1));
  V3 b=norm_x(cross_x(u0,u2));
  float st = dot_x(cross_x(u1,u2), u0);
  float sgn = (st>0.f)?1.f:((st<0.f)?-1.f:0.f);
  float r = __fmul_rn(sgn, acos_xla(dot_x(a,b)));
  if (isnan(r)) r = 0.f;
  return r;
}
__device__ __forceinline__ void comp_cb(const float* p, float* cb){
  float bx=p[3]-p[0], by=p[4]-p[1], bz=p[5]-p[2];
  float cx=p[6]-p[3], cy=p[7]-p[4], cz=p[8]-p[5];
  float ax = by*cz - bz*cy, ay = bz*cx - bx*cz, az = bx*cy - by*cx;
  cb[0] = -0.58273431f*ax + 0.56802827f*bx - 0.54067466f*cx + p[3];
  cb[1] = -0.58273431f*ay + 0.56802827f*by - 0.54067466f*cy + p[4];
  cb[2] = -0.58273431f*az + 0.56802827f*bz - 0.54067466f*cz + p[5];
}
__device__ __forceinline__ unsigned smem_u32(const void* p){
  unsigned a;
  asm("{ .reg .u64 t; cvta.to.shared.u64 t, %1; cvt.u32.u64 %0, t; }" : "=r"(a) : "l"(p));
  return a;
}

// =====================================================================
// Kernel 0a: W_edge rows 65..467 -> fp16 SW128-chunk image
// =====================================================================
__global__ void wconv_kernel(const float* __restrict__ We){
  int idx = blockIdx.x*256 + threadIdx.x;           // 7*128*64 = 57344
  if (idx >= NCHUNK*128*64) return;
  int c  = idx / (128*64);
  int r  = idx % (128*64);
  int n  = r >> 6;
  int kk = r & 63;
  int kg = c*64 + kk;
  float v = (kg < 403) ? We[(65+kg)*NF + n] : 0.0f;
  unsigned off = ((unsigned)(n>>3)*1024) | ((unsigned)(n&7)*128) | (unsigned)(kk*2);
  *(__half*)(g_Bhalf + c*BCH + SWZ(off)) = __float2half_rn(v);
}

// =====================================================================
// Kernel 0b: pack (Ca.xyz, mask) for coalesced KNN loads
// =====================================================================
__global__ void pack_kernel(const float* __restrict__ X, const float* __restrict__ mask){
  int g = blockIdx.x*256 + threadIdx.x;
  if (g >= Bn*Ln) return;
  g_ca[g] = make_float4(X[(size_t)g*12+3], X[(size_t)g*12+4], X[(size_t)g*12+5], mask[g]);
}

// =====================================================================
// Kernel 1: masked distances + register-resident two-stage top-K
// =====================================================================
__global__ void __launch_bounds__(256) knn_kernel(
    const float* __restrict__ X, float* __restrict__ out)
{
  __shared__ float Dv[Ln];
  __shared__ float fred[8];
  __shared__ u64 wtop[8*32];

  int tid = threadIdx.x;
  int g = blockIdx.x;
  int b = g >> 11;
  int i = g & (Ln-1);
  const float4* Cb = g_ca + b*Ln;
  float4 ci = g_ca[g];
  float cax = ci.x, cay = ci.y, caz = ci.z, mi = ci.w;

  float lmax = 0.0f;
  float m2v[8];
  #pragma unroll
  for (int q=0;q<8;q++){
    int j = tid + q*256;
    float4 cj = Cb[j];
    float dx = __fsub_rn(cax, cj.x);
    float dy = __fsub_rn(cay, cj.y);
    float dz = __fsub_rn(caz, cj.z);
    float m2 = __fmul_rn(mi, cj.w);
    float ss = __fadd_rn(
        __fmaf_rn(dz, dz, __fmaf_rn(dx, dx, __fmul_rn(dy, dy))), 1e-6f);
    float D = __fmul_rn(m2, __fsqrt_rn(ss));
    Dv[j] = D; m2v[q] = m2;
    lmax = fmaxf(lmax, D);
  }
  #pragma unroll
  for (int o=16;o;o>>=1) lmax = fmaxf(lmax, __shfl_xor_sync(0xffffffffu, lmax, o));
  if ((tid&31)==0) fred[tid>>5] = lmax;
  __syncthreads();
  float Dmax = fred[0];
  #pragma unroll
  for (int q=1;q<8;q++) Dmax = fmaxf(Dmax, fred[q]);
  #pragma unroll
  for (int q=0;q<8;q++){
    int j = tid + q*256;
    Dv[j] = __fadd_rn(Dv[j],
            __fmul_rn(__fmul_rn(2.0f, __fsub_rn(1.0f, m2v[q])), Dmax));
  }
  __syncthreads();

  // Stage A: per-warp top-32 over registers (lane owns 8 contiguous j)
  int w = tid >> 5, lane = tid & 31;
  u64 key[8];
  #pragma unroll
  for (int q=0;q<8;q++){
    int j = tid*8 + q;
    key[q] = ((u64)__float_as_uint(Dv[j]) << 32) | (unsigned)j;
  }
  for (int k=0;k<Kn;k++){
    u64 m = key[0];
    #pragma unroll
    for (int q=1;q<8;q++) m = (key[q] < m) ? key[q] : m;
    #pragma unroll
    for (int o=16;o;o>>=1){
      u64 other = __shfl_xor_sync(0xffffffffu, m, o);
      m = (other < m) ? other : m;
    }
    #pragma unroll
    for (int q=0;q<8;q++) if (key[q] == m) key[q] = ~0ull;
    if (lane==0) wtop[w*32 + k] = m;
  }
  __syncthreads();

  // Stage B: warp 0 merges 8x32 candidates
  if (w == 0){
    u64 cnd[8];
    #pragma unroll
    for (int q=0;q<8;q++) cnd[q] = wtop[lane*8 + q];
    int base = g*Kn;
    for (int k=0;k<Kn;k++){
      u64 m = cnd[0];
      #pragma unroll
      for (int q=1;q<8;q++) m = (cnd[q] < m) ? cnd[q] : m;
      #pragma unroll
      for (int o=16;o;o>>=1){
        u64 other = __shfl_xor_sync(0xffffffffu, m, o);
        m = (other < m) ? other : m;
      }
      #pragma unroll
      for (int q=0;q<8;q++) if (cnd[q] == m) cnd[q] = ~0ull;
      if (lane==0){
        int bj = (int)(m & 0xffffffffull);
        g_eidx[base+k] = bj;
        out[EIDX_OFF + base + k] = (float)bj;
      }
    }
  }
  if (tid < 12) out[X_OFF + (size_t)g*12 + tid] = X[(size_t)(b*Ln+i)*12 + tid];
}

// =====================================================================
// Kernel 2: node features -> row-lookup GEMM -> LN (unchanged)
// =====================================================================
__global__ void __launch_bounds__(128) node_kernel(
    const int* __restrict__ S, const float* __restrict__ BB, const float* __restrict__ SC,
    const float* __restrict__ Wn, const float* __restrict__ bn,
    const float* __restrict__ gn, const float* __restrict__ betan,
    float* __restrict__ out)
{
  __shared__ float sv[14];
  __shared__ float red1[4];
  __shared__ float red2[4];
  int g = blockIdx.x;
  int f = threadIdx.x;
  if (f < 6) sv[f] = BB[g*6 + f];
  else if (f < 14) sv[f] = SC[g*8 + (f-6)];
  __syncthreads();
  int s = S[g];
  float h = bn[f] + Wn[s*NF + f];
  #pragma unroll
  for (int j=0;j<6;j++)  h = fmaf(sv[j],   Wn[(21+j)*NF + f], h);
  #pragma unroll
  for (int j=0;j<8;j++)  h = fmaf(sv[6+j], Wn[(27+j)*NF + f], h);

  int lane = f & 31, wid = f >> 5;
  float t = h;
  #pragma unroll
  for (int o=16;o;o>>=1) t += __shfl_xor_sync(0xffffffffu, t, o);
  if (lane==0) red1[wid] = t;
  __syncthreads();
  float mean = (red1[0]+red1[1]+red1[2]+red1[3]) * (1.0f/128.0f);
  float d = h - mean;
  float t2 = d*d;
  #pragma unroll
  for (int o=16;o;o>>=1) t2 += __shfl_xor_sync(0xffffffffu, t2, o);
  if (lane==0) red2[wid] = t2;
  __syncthreads();
  float var = (red2[0]+red2[1]+red2[2]+red2[3]) * (1.0f/128.0f);
  out[HV_OFF + (size_t)g*NF + f] = d / sqrtf(var + 1e-5f) * gn[f] + betan[f];
}

// =====================================================================
// Kernel 3: edge features -> fp16 A chunks + HMMA + LN
// Block: 2 nodes = 64 edges, 256 threads, 8 warps.
// smem: misc 1KB | A: 7 x 8KB | B: 2 x 16KB double buffer  (~89KB -> 2 CTA/SM)
// B streamed via cp.async, prefetched under Phase A / previous MMA.
// =====================================================================
#define SM_X5I   64         // 2*15 floats
#define SM_POS   320        // 64 ints
#define SM_A     1024
#define SM_B     (SM_A + NCHUNK*ACH)               // 58368
#define EDGE_SMEM (SM_B + 2*BCH)                   // 91136
#define CSTRIDE  132

__device__ __forceinline__ void prefetch_chunk(unsigned smb, int c, int buf, int tid){
  unsigned dst = smb + SM_B + (unsigned)buf*BCH + (unsigned)tid*16;
  const char* src = (const char*)g_Bhalf + c*BCH + tid*16;
  #pragma unroll
  for (int it=0;it<4;it++)
    asm volatile("cp.async.cg.shared.global [%0], [%1], 16;"
                 :: "r"(dst + it*4096u), "l"(src + it*4096) : "memory");
  asm volatile("cp.async.commit_group;" ::: "memory");
}

__global__ void __launch_bounds__(256) edge_kernel(
    const float* __restrict__ X, const int* __restrict__ chain,
    const float* __restrict__ We, const float* __restrict__ be,
    const float* __restrict__ ge, const float* __restrict__ betae,
    float* __restrict__ out)
{
  extern __shared__ char sm[];
  unsigned smb = smem_u32(sm);
  float* x5i = (float*)(sm + SM_X5I);
  int*   pos = (int*)(sm + SM_POS);

  int tid = threadIdx.x;
  int wid = tid >> 5, lane = tid & 31;
  int g0 = blockIdx.x * 2;
  int b  = g0 >> 11;

  // prefetch first two B chunks under Phase A
  prefetch_chunk(smb, 0, 0, tid);
  prefetch_chunk(smb, 1, 1, tid);

  if (tid < 24){
    int nl = tid / 12, c = tid % 12;
    x5i[nl*15 + c] = X[(size_t)(g0+nl)*12 + c];
  }
  __syncthreads();
  if (tid < 2) comp_cb(x5i + tid*15, x5i + tid*15 + 12);
  __syncthreads();

  // ---------- Phase A: features -> fp16 SW128 A chunks ----------
  {
    int e   = tid >> 2;        // edge 0..63
    int sub = tid & 3;
    int nl  = e >> 5;
    int k   = e & 31;
    int gi  = g0 + nl;
    int i   = gi & (Ln-1);
    int j   = g_eidx[gi*Kn + k];
    const float* Xb = X + (size_t)b*Ln*12;

    float n5[15];
    #pragma unroll
    for (int c=0;c<12;c++) n5[c] = Xb[(size_t)j*12 + c];
    comp_cb(n5, n5+12);
    const float* P = x5i + nl*15;
    unsigned rowatom = (unsigned)(e>>3)*1024;
    unsigned rin     = (unsigned)(e&7)*128;

    for (int p = sub; p < 25; p += 4){
      int a = p/5, q = p%5;
      float dx = P[a*3+0]-n5[q*3+0];
      float dy = P[a*3+1]-n5[q*3+1];
      float dz = P[a*3+2]-n5[q*3+2];
      float d = sqrtf(dx*dx + dy*dy + dz*dz + 1e-6f);
      unsigned h2[8];
      #pragma unroll
      for (int r2=0;r2<8;r2++){
        float mu0 = (float)(2*r2)   * (20.0f/15.0f);
        float mu1 = (float)(2*r2+1) * (20.0f/15.0f);
        float t0 = (d - mu0) * 0.8f;
        float t1 = (d - mu1) * 0.8f;
        __half2 hh = __floats2half2_rn(__expf(-t0*t0), __expf(-t1*t1));
        h2[r2] = *(unsigned*)&hh;
      }
      int c = p >> 2;
      unsigned kb = (unsigned)(p&3)*32;
      char* base = sm + SM_A + c*ACH + rowatom;
      *(uint4*)(base + SWZ(rin + kb))      = make_uint4(h2[0],h2[1],h2[2],h2[3]);
      *(uint4*)(base + SWZ(rin + kb + 16)) = make_uint4(h2[4],h2[5],h2[6],h2[7]);
    }
    if (sub == 1){
      float et = (chain[b*Ln + j] == chain[gi]) ? 2.0f : 1.0f;
      V3 Ni  = {P[0],P[1],P[2]},  Cai = {P[3],P[4],P[5]},  Ci = {P[6],P[7],P[8]};
      V3 Nj  = {n5[0],n5[1],n5[2]}, Caj = {n5[3],n5[4],n5[5]}, Cj = {n5[6],n5[7],n5[8]};
      float d0 = dihedral(Ci, Nj, Caj, Cj);
      float d1 = dihedral(Ni, Cai, Ci, Nj);
      __half2 hh0 = __floats2half2_rn(et, d0);
      __half2 hh1 = __floats2half2_rn(d1, 0.f);
      char* base = sm + SM_A + 6*ACH + rowatom;
      *(uint4*)(base + SWZ(rin + 32)) = make_uint4(*(unsigned*)&hh0, *(unsigned*)&hh1, 0u, 0u);
      #pragma unroll
      for (int s4=1;s4<6;s4++)
        *(uint4*)(base + SWZ(rin + 32 + (unsigned)s4*16)) = make_uint4(0u,0u,0u,0u);
      int offp = j - i + 32;
      pos[e] = min(max(offp, 0), 64);
    }
  }
  __syncthreads();

  // ---------- HMMA: warp w -> rows (w&1)*32..+31, cols (w>>1)*32..+31 ----------
  int mr0 = (wid & 1) * 32;
  int nc0 = (wid >> 1) * 32;
  float acc[2][4][4];
  #pragma unroll
  for (int mt=0;mt<2;mt++)
    #pragma unroll
    for (int nt=0;nt<4;nt++)
      #pragma unroll
      for (int q=0;q<4;q++) acc[mt][nt][q] = 0.f;

  for (int c = 0; c < NCHUNK; c++){
    asm volatile("cp.async.wait_group 1;" ::: "memory");
    __syncthreads();                       // chunk c resident in buf c&1
    unsigned CA = smb + SM_A + c*ACH;
    unsigned CB = smb + SM_B + (unsigned)(c&1)*BCH;
    #pragma unroll
    for (int ks = 0; ks < 4; ks++){
      unsigned kb = (unsigned)ks*32;
      unsigned af[2][4];
      #pragma unroll
      for (int mt=0;mt<2;mt++){
        int r = mr0 + mt*16 + (lane & 15);
        unsigned sel = (unsigned)(lane >> 4) * 16;
        unsigned addr = CA + (unsigned)(r>>3)*1024 + SWZ((unsigned)(r&7)*128 + kb + sel);
        asm volatile("ldmatrix.sync.aligned.m8n8.x4.shared.b16 {%0,%1,%2,%3}, [%4];"
          : "=r"(af[mt][0]), "=r"(af[mt][1]), "=r"(af[mt][2]), "=r"(af[mt][3]) : "r"(addr));
      }
      unsigned bf[4][2];
      #pragma unroll
      for (int nt=0;nt<4;nt++){
        int lm = lane & 15;
        int n = nc0 + nt*8 + (lm & 7);
        unsigned sel = (unsigned)((lm >> 3) & 1) * 16;
        unsigned addr = CB + (unsigned)(n>>3)*1024 + SWZ((unsigned)(n&7)*128 + kb + sel);
        asm volatile("ldmatrix.sync.aligned.m8n8.x2.shared.b16 {%0,%1}, [%2];"
          : "=r"(bf[nt][0]), "=r"(bf[nt][1]) : "r"(addr));
      }
      #pragma unroll
      for (int mt=0;mt<2;mt++)
        #pragma unroll
        for (int nt=0;nt<4;nt++)
          asm volatile(
            "mma.sync.aligned.m16n8k16.row.col.f32.f16.f16.f32 "
            "{%0,%1,%2,%3}, {%4,%5,%6,%7}, {%8,%9}, {%0,%1,%2,%3};"
            : "+f"(acc[mt][nt][0]), "+f"(acc[mt][nt][1]),
              "+f"(acc[mt][nt][2]), "+f"(acc[mt][nt][3])
            : "r"(af[mt][0]), "r"(af[mt][1]), "r"(af[mt][2]), "r"(af[mt][3]),
              "r"(bf[nt][0]), "r"(bf[nt][1]));
    }
    __syncthreads();                       // all warps done reading buf c&1
    if (c+2 < NCHUNK) prefetch_chunk(smb, c+2, c&1, tid);
  }
  __syncthreads();                         // A region free -> reuse as C

  // ---------- D -> smem C [64][CSTRIDE] ----------
  {
    float* C = (float*)(sm + SM_A);
    #pragma unroll
    for (int mt=0;mt<2;mt++)
      #pragma unroll
      for (int nt=0;nt<4;nt++){
        int row = mr0 + mt*16 + (lane >> 2);
        int col = nc0 + nt*8 + 2*(lane & 3);
        C[row*CSTRIDE + col]       = acc[mt][nt][0];
        C[row*CSTRIDE + col + 1]   = acc[mt][nt][1];
        C[(row+8)*CSTRIDE + col]   = acc[mt][nt][2];
        C[(row+8)*CSTRIDE + col+1] = acc[mt][nt][3];
      }
  }
  __syncthreads();

  // ---------- Epilogue: bias + one-hot row (fp32 exact) + LN ----------
  {
    const float* C = (const float*)(sm + SM_A);
    int row = tid >> 2, seg = tid & 3;
    const float* Wrow = We + (size_t)pos[row]*NF;
    float y[32];
    float sum = 0.f, sumsq = 0.f;
    #pragma unroll
    for (int q=0;q<32;q++){
      int f = seg*32 + q;
      float v = C[row*CSTRIDE + f] + be[f] + Wrow[f];
      y[q] = v; sum += v; sumsq += v*v;
    }
    sum   += __shfl_xor_sync(0xffffffffu, sum, 1);
    sum   += __shfl_xor_sync(0xffffffffu, sum, 2);
    sumsq += __shfl_xor_sync(0xffffffffu, sumsq, 1);
    sumsq += __shfl_xor_sync(0xffffffffu, sumsq, 2);
    float mean = sum * (1.0f/128.0f);
    float var  = sumsq * (1.0f/128.0f) - mean*mean;
    float inv  = 1.0f / sqrtf(var + 1e-5f);

    int nl = row >> 5, k2 = row & 31;
    float* O = out + HE_OFF + ((size_t)(g0+nl)*Kn + k2)*NF + seg*32;
    #pragma unroll
    for (int q=0;q<32;q+=4){
      int f = seg*32 + q;
      float4 o4;
      o4.x = (y[q]   - mean)*inv*ge[f]   + betae[f];
      o4.y = (y[q+1] - mean)*inv*ge[f+1] + betae[f+1];
      o4.z = (y[q+2] - mean)*inv*ge[f+2] + betae[f+2];
      o4.w = (y[q+3] - mean)*inv*ge[f+3] + betae[f+3];
      *(float4*)(O + q) = o4;
    }
  }
}

extern "C" void kernel_launch(void* const* d_in, const int* in_sizes, int n_in,
                              void* d_out, int out_size) {
  (void)in_sizes; (void)n_in; (void)out_size;
  const float* X     = (const float*)d_in[0];
  const int*   S     = (const int*)  d_in[1];
  const float* BB    = (const float*)d_in[2];
  const float* SC    = (const float*)d_in[3];
  const int*   chain = (const int*)  d_in[4];
  const float* mask  = (const float*)d_in[5];
  const float* Wn    = (const float*)d_in[6];
  const float* bn    = (const float*)d_in[7];
  const float* gn    = (const float*)d_in[8];
  const float* betan = (const float*)d_in[9];
  const float* We    = (const float*)d_in[10];
  const float* be    = (const float*)d_in[11];
  const float* ge    = (const float*)d_in[12];
  const float* betae = (const float*)d_in[13];
  float* out = (float*)d_out;

  cudaFuncSetAttribute(edge_kernel, cudaFuncAttributeMaxDynamicSharedMemorySize, EDGE_SMEM);

  wconv_kernel<<<(NCHUNK*128*64 + 255)/256, 256>>>(We);
  pack_kernel <<<(Bn*Ln + 255)/256, 256>>>(X, mask);
  knn_kernel  <<<Bn*Ln, 256>>>(X, out);
  node_kernel <<<Bn*Ln, 128>>>(S, BB, SC, Wn, bn, gn, betan, out);
  edge_kernel <<<Bn*Ln/2, 256, EDGE_SMEM>>>(X, chain, We, be, ge, betae, out);
}

// round 15
// speedup vs baseline: 1.6658x; 1.1259x over previous
#include <cuda_runtime.h>
#include <cuda_fp16.h>
#include <math.h>

#define Bn 2
#define Ln 2048
#define Kn 32
#define NF 128

#define HV_OFF   0
#define HE_OFF   (Bn*Ln*NF)                        // 524288
#define EIDX_OFF (HE_OFF + Bn*Ln*Kn*NF)            // 17301504
#define X_OFF    (EIDX_OFF + Bn*Ln*Kn)             // 17432576

// GEMM: 64 edges (2 nodes) per block, K 403 -> 448 (7 chunks of 64 fp16)
#define NCHUNK 7
#define ACH 8192                 // A chunk: 64 rows x 128B
#define BCH 16384                // B chunk: 128 rows x 128B

__device__ int g_eidx[Bn*Ln*Kn];
__device__ __align__(16) unsigned char g_Bhalf[NCHUNK*BCH];  // W fp16, SW128 chunk image
__device__ __align__(16) float4 g_ca[Bn*Ln];                 // packed (Ca.xyz, mask)

typedef unsigned long long u64;

#define SWZ(o) ((o) ^ (((o) >> 3) & 0x70))

// ---------- r11-exact math chain (div.full.f32 normalize — passing config) ----------
struct V3 { float x,y,z; };
__device__ __forceinline__ V3 vsub(V3 a, V3 b){
  V3 r; r.x=__fsub_rn(a.x,b.x); r.y=__fsub_rn(a.y,b.y); r.z=__fsub_rn(a.z,b.z); return r;
}
__device__ __forceinline__ V3 cross_x(V3 a, V3 b){
  V3 r;
  r.x = __fmaf_rn(a.y, b.z, -__fmul_rn(a.z, b.y));
  r.y = __fmaf_rn(a.z, b.x, -__fmul_rn(a.x, b.z));
  r.z = __fmaf_rn(a.x, b.y, -__fmul_rn(a.y, b.x));
  return r;
}
__device__ __forceinline__ float dot_x(V3 a, V3 b){
  return __fmaf_rn(a.z, b.z, __fmaf_rn(a.x, b.x, __fmul_rn(a.y, b.y)));
}
__device__ __forceinline__ float n2n(float x){
  if (isnan(x)) return 0.0f;
  if (isinf(x)) return copysignf(3.402823466e38f, x);
  return x;
}
__device__ __forceinline__ float div_full(float a, float b){
  float r; asm("div.full.f32 %0, %1, %2;" : "=f"(r) : "f"(a), "f"(b)); return r;
}
__device__ __forceinline__ V3 norm_x(V3 v){
  float n = __fsqrt_rn(dot_x(v,v));
  V3 r;
  r.x = n2n(div_full(v.x, n));
  r.y = n2n(div_full(v.y, n));
  r.z = n2n(div_full(v.z, n));
  return r;
}
__device__ __forceinline__ float acos_xla(float x){
  if (x == -1.0f) return 3.14159265358979323846f;
  float t = __fmaf_rn(-x, x, 1.0f);
  float s = __fsqrt_rn(t);
  return __fmul_rn(2.0f, atan2f(s, __fadd_rn(1.0f, x)));
}
__device__ __forceinline__ float dihedral(V3 p0, V3 p1, V3 p2, V3 p3){
  V3 u0=vsub(p2,p1), u1=vsub(p0,p1), u2=vsub(p3,p2);
  V3 a=norm_x(cross_x(u0,u1));
  V3 b=norm_x(cross_x(u0,u2));
  float st = dot_x(cross_x(u1,u2), u0);
  float sgn = (st>0.f)?1.f:((st<0.f)?-1.f:0.f);
  float r = __fmul_rn(sgn, acos_xla(dot_x(a,b)));
  if (isnan(r)) r = 0.f;
  return r;
}
__device__ __forceinline__ void comp_cb(const float* p, float* cb){
  float bx=p[3]-p[0], by=p[4]-p[1], bz=p[5]-p[2];
  float cx=p[6]-p[3], cy=p[7]-p[4], cz=p[8]-p[5];
  float ax = by*cz - bz*cy, ay = bz*cx - bx*cz, az = bx*cy - by*cx;
  cb[0] = -0.58273431f*ax + 0.56802827f*bx - 0.54067466f*cx + p[3];
  cb[1] = -0.58273431f*ay + 0.56802827f*by - 0.54067466f*cy + p[4];
  cb[2] = -0.58273431f*az + 0.56802827f*bz - 0.54067466f*cz + p[5];
}
__device__ __forceinline__ unsigned smem_u32(const void* p){
  unsigned a;
  asm("{ .reg .u64 t; cvta.to.shared.u64 t, %1; cvt.u32.u64 %0, t; }" : "=r"(a) : "l"(p));
  return a;
}
__device__ __forceinline__ unsigned redux_min(unsigned v){
  unsigned r; asm("redux.sync.min.u32 %0, %1, 0xffffffff;" : "=r"(r) : "r"(v)); return r;
}

// =====================================================================
// Kernel 0a: W_edge rows 65..467 -> fp16 SW128-chunk image
// =====================================================================
__global__ void wconv_kernel(const float* __restrict__ We){
  int idx = blockIdx.x*256 + threadIdx.x;           // 7*128*64 = 57344
  if (idx >= NCHUNK*128*64) return;
  int c  = idx / (128*64);
  int r  = idx % (128*64);
  int n  = r >> 6;
  int kk = r & 63;
  int kg = c*64 + kk;
  float v = (kg < 403) ? We[(65+kg)*NF + n] : 0.0f;
  unsigned off = ((unsigned)(n>>3)*1024) | ((unsigned)(n&7)*128) | (unsigned)(kk*2);
  *(__half*)(g_Bhalf + c*BCH + SWZ(off)) = __float2half_rn(v);
}

// =====================================================================
// Kernel 0b: pack (Ca.xyz, mask) for coalesced KNN loads
// =====================================================================
__global__ void pack_kernel(const float* __restrict__ X, const float* __restrict__ mask){
  int g = blockIdx.x*256 + threadIdx.x;
  if (g >= Bn*Ln) return;
  g_ca[g] = make_float4(X[(size_t)g*12+3], X[(size_t)g*12+4], X[(size_t)g*12+5], mask[g]);
}

// =====================================================================
// Kernel 1: masked distances + two-stage top-K (redux.sync extraction)
// =====================================================================
__global__ void __launch_bounds__(256) knn_kernel(
    const float* __restrict__ X, float* __restrict__ out)
{
  __shared__ float Dv[Ln];
  __shared__ float fred[8];
  __shared__ u64 wtop[8*32];

  int tid = threadIdx.x;
  int g = blockIdx.x;
  int b = g >> 11;
  int i = g & (Ln-1);
  const float4* Cb = g_ca + b*Ln;
  float4 ci = g_ca[g];
  float cax = ci.x, cay = ci.y, caz = ci.z, mi = ci.w;

  float lmax = 0.0f;
  float m2v[8];
  #pragma unroll
  for (int q=0;q<8;q++){
    int j = tid + q*256;
    float4 cj = Cb[j];
    float dx = __fsub_rn(cax, cj.x);
    float dy = __fsub_rn(cay, cj.y);
    float dz = __fsub_rn(caz, cj.z);
    float m2 = __fmul_rn(mi, cj.w);
    float ss = __fadd_rn(
        __fmaf_rn(dz, dz, __fmaf_rn(dx, dx, __fmul_rn(dy, dy))), 1e-6f);
    float D = __fmul_rn(m2, __fsqrt_rn(ss));
    Dv[j] = D; m2v[q] = m2;
    lmax = fmaxf(lmax, D);
  }
  #pragma unroll
  for (int o=16;o;o>>=1) lmax = fmaxf(lmax, __shfl_xor_sync(0xffffffffu, lmax, o));
  if ((tid&31)==0) fred[tid>>5] = lmax;
  __syncthreads();
  float Dmax = fred[0];
  #pragma unroll
  for (int q=1;q<8;q++) Dmax = fmaxf(Dmax, fred[q]);
  #pragma unroll
  for (int q=0;q<8;q++){
    int j = tid + q*256;
    Dv[j] = __fadd_rn(Dv[j],
            __fmul_rn(__fmul_rn(2.0f, __fsub_rn(1.0f, m2v[q])), Dmax));
  }
  __syncthreads();

  // Stage A: per-warp top-32 (lane owns 8 contiguous j); extraction via redux
  int w = tid >> 5, lane = tid & 31;
  u64 key[8];
  #pragma unroll
  for (int q=0;q<8;q++){
    int j = tid*8 + q;
    key[q] = ((u64)__float_as_uint(Dv[j]) << 32) | (unsigned)j;
  }
  for (int k=0;k<Kn;k++){
    u64 m = key[0];
    #pragma unroll
    for (int q=1;q<8;q++) m = (key[q] < m) ? key[q] : m;
    unsigned d32 = (unsigned)(m >> 32);
    unsigned dmin = redux_min(d32);
    unsigned cand = (d32 == dmin) ? (unsigned)m : 0xFFFFFFFFu;
    unsigned imin = redux_min(cand);
    u64 sel = ((u64)dmin << 32) | imin;
    #pragma unroll
    for (int q=0;q<8;q++) if (key[q] == sel) key[q] = ~0ull;
    if (lane==0) wtop[w*32 + k] = sel;
  }
  __syncthreads();

  // Stage B: warp 0 merges 8x32 candidates (same redux extraction)
  if (w == 0){
    u64 cnd[8];
    #pragma unroll
    for (int q=0;q<8;q++) cnd[q] = wtop[lane*8 + q];
    int base = g*Kn;
    for (int k=0;k<Kn;k++){
      u64 m = cnd[0];
      #pragma unroll
      for (int q=1;q<8;q++) m = (cnd[q] < m) ? cnd[q] : m;
      unsigned d32 = (unsigned)(m >> 32);
      unsigned dmin = redux_min(d32);
      unsigned cand = (d32 == dmin) ? (unsigned)m : 0xFFFFFFFFu;
      unsigned imin = redux_min(cand);
      u64 sel = ((u64)dmin << 32) | imin;
      #pragma unroll
      for (int q=0;q<8;q++) if (cnd[q] == sel) cnd[q] = ~0ull;
      if (lane==0){
        int bj = (int)imin;
        g_eidx[base+k] = bj;
        out[EIDX_OFF + base + k] = (float)bj;
      }
    }
  }
  if (tid < 12) out[X_OFF + (size_t)g*12 + tid] = X[(size_t)(b*Ln+i)*12 + tid];
}

// =====================================================================
// Kernel 2: node features -> row-lookup GEMM -> LN (unchanged)
// =====================================================================
__global__ void __launch_bounds__(128) node_kernel(
    const int* __restrict__ S, const float* __restrict__ BB, const float* __restrict__ SC,
    const float* __restrict__ Wn, const float* __restrict__ bn,
    const float* __restrict__ gn, const float* __restrict__ betan,
    float* __restrict__ out)
{
  __shared__ float sv[14];
  __shared__ float red1[4];
  __shared__ float red2[4];
  int g = blockIdx.x;
  int f = threadIdx.x;
  if (f < 6) sv[f] = BB[g*6 + f];
  else if (f < 14) sv[f] = SC[g*8 + (f-6)];
  __syncthreads();
  int s = S[g];
  float h = bn[f] + Wn[s*NF + f];
  #pragma unroll
  for (int j=0;j<6;j++)  h = fmaf(sv[j],   Wn[(21+j)*NF + f], h);
  #pragma unroll
  for (int j=0;j<8;j++)  h = fmaf(sv[6+j], Wn[(27+j)*NF + f], h);

  int lane = f & 31, wid = f >> 5;
  float t = h;
  #pragma unroll
  for (int o=16;o;o>>=1) t += __shfl_xor_sync(0xffffffffu, t, o);
  if (lane==0) red1[wid] = t;
  __syncthreads();
  float mean = (red1[0]+red1[1]+red1[2]+red1[3]) * (1.0f/128.0f);
  float d = h - mean;
  float t2 = d*d;
  #pragma unroll
  for (int o=16;o;o>>=1) t2 += __shfl_xor_sync(0xffffffffu, t2, o);
  if (lane==0) red2[wid] = t2;
  __syncthreads();
  float var = (red2[0]+red2[1]+red2[2]+red2[3]) * (1.0f/128.0f);
  out[HV_OFF + (size_t)g*NF + f] = d / sqrtf(var + 1e-5f) * gn[f] + betan[f];
}

// =====================================================================
// Kernel 3: edge features -> fp16 A (two 4-chunk passes) + HMMA + LN
// Block: 2 nodes = 64 edges, 256 threads, 8 warps.
// smem: misc 1KB | A: 4 x 8KB (reused per half) | B: 2 x 16KB  = 65KB -> 3 CTA/SM
// =====================================================================
#define SM_X5I   64         // 2*15 floats
#define SM_POS   320        // 64 ints
#define SM_A     1024
#define SM_B     (SM_A + 4*ACH)                    // 33792
#define EDGE_SMEM (SM_B + 2*BCH)                   // 66560
#define CSTRIDE  132        // C: 64*132*4 = 33792B at SM_A (overlaps dead B buf0 tail)

__device__ __forceinline__ void prefetch_chunk(unsigned smb, int c, int buf, int tid){
  unsigned dst = smb + SM_B + (unsigned)buf*BCH + (unsigned)tid*16;
  const char* src = (const char*)g_Bhalf + c*BCH + tid*16;
  #pragma unroll
  for (int it=0;it<4;it++)
    asm volatile("cp.async.cg.shared.global [%0], [%1], 16;"
                 :: "r"(dst + it*4096u), "l"(src + it*4096) : "memory");
  asm volatile("cp.async.commit_group;" ::: "memory");
}

__global__ void __launch_bounds__(256, 3) edge_kernel(
    const float* __restrict__ X, const int* __restrict__ chain,
    const float* __restrict__ We, const float* __restrict__ be,
    const float* __restrict__ ge, const float* __restrict__ betae,
    float* __restrict__ out)
{
  extern __shared__ char sm[];
  unsigned smb = smem_u32(sm);
  float* x5i = (float*)(sm + SM_X5I);
  int*   pos = (int*)(sm + SM_POS);

  int tid = threadIdx.x;
  int wid = tid >> 5, lane = tid & 31;
  int g0 = blockIdx.x * 2;
  int b  = g0 >> 11;

  // prefetch first two B chunks under Phase A half 0
  prefetch_chunk(smb, 0, 0, tid);
  prefetch_chunk(smb, 1, 1, tid);

  if (tid < 24){
    int nl = tid / 12, c = tid % 12;
    x5i[nl*15 + c] = X[(size_t)(g0+nl)*12 + c];
  }
  __syncthreads();
  if (tid < 2) comp_cb(x5i + tid*15, x5i + tid*15 + 12);
  __syncthreads();

  // per-edge geometry (held in registers across both halves)
  int e   = tid >> 2;        // edge 0..63
  int sub = tid & 3;
  int nl  = e >> 5;
  int k   = e & 31;
  int gi  = g0 + nl;
  int i   = gi & (Ln-1);
  int j   = g_eidx[gi*Kn + k];
  const float* Xb = X + (size_t)b*Ln*12;
  float n5[15];
  #pragma unroll
  for (int c=0;c<12;c++) n5[c] = Xb[(size_t)j*12 + c];
  comp_cb(n5, n5+12);
  const float* P = x5i + nl*15;
  unsigned rowatom = (unsigned)(e>>3)*1024;
  unsigned rin     = (unsigned)(e&7)*128;

  // MMA accumulators: warp w -> rows (w&1)*32..+31, cols (w>>1)*32..+31
  int mr0 = (wid & 1) * 32;
  int nc0 = (wid >> 1) * 32;
  float acc[2][4][4];
  #pragma unroll
  for (int mt=0;mt<2;mt++)
    #pragma unroll
    for (int nt=0;nt<4;nt++)
      #pragma unroll
      for (int q=0;q<4;q++) acc[mt][nt][q] = 0.f;

  #pragma unroll
  for (int h=0; h<2; h++){
    // ---------- Phase A half h: features -> A bufs 0..3 (chunks h*4 .. ) ----------
    int pstart = h==0 ? sub : 16+sub;
    int pend   = h==0 ? 16 : 25;
    for (int p = pstart; p < pend; p += 4){
      int a = p/5, q = p%5;
      float dx = P[a*3+0]-n5[q*3+0];
      float dy = P[a*3+1]-n5[q*3+1];
      float dz = P[a*3+2]-n5[q*3+2];
      float d = sqrtf(dx*dx + dy*dy + dz*dz + 1e-6f);
      unsigned h2[8];
      #pragma unroll
      for (int r2=0;r2<8;r2++){
        float mu0 = (float)(2*r2)   * (20.0f/15.0f);
        float mu1 = (float)(2*r2+1) * (20.0f/15.0f);
        float t0 = (d - mu0) * 0.8f;
        float t1 = (d - mu1) * 0.8f;
        __half2 hh = __floats2half2_rn(__expf(-t0*t0), __expf(-t1*t1));
        h2[r2] = *(unsigned*)&hh;
      }
      int cb2 = (p >> 2) - h*4;
      unsigned kb = (unsigned)(p&3)*32;
      char* base = sm + SM_A + cb2*ACH + rowatom;
      *(uint4*)(base + SWZ(rin + kb))      = make_uint4(h2[0],h2[1],h2[2],h2[3]);
      *(uint4*)(base + SWZ(rin + kb + 16)) = make_uint4(h2[4],h2[5],h2[6],h2[7]);
    }
    if (h==1 && sub == 1){
      float et = (chain[b*Ln + j] == chain[gi]) ? 2.0f : 1.0f;
      V3 Ni  = {P[0],P[1],P[2]},  Cai = {P[3],P[4],P[5]},  Ci = {P[6],P[7],P[8]};
      V3 Nj  = {n5[0],n5[1],n5[2]}, Caj = {n5[3],n5[4],n5[5]}, Cj = {n5[6],n5[7],n5[8]};
      float d0 = dihedral(Ci, Nj, Caj, Cj);
      float d1 = dihedral(Ni, Cai, Ci, Nj);
      __half2 hh0 = __floats2half2_rn(et, d0);
      __half2 hh1 = __floats2half2_rn(d1, 0.f);
      char* base = sm + SM_A + 2*ACH + rowatom;      // chunk 6 -> buf 2
      *(uint4*)(base + SWZ(rin + 32)) = make_uint4(*(unsigned*)&hh0, *(unsigned*)&hh1, 0u, 0u);
      #pragma unroll
      for (int s4=1;s4<6;s4++)
        *(uint4*)(base + SWZ(rin + 32 + (unsigned)s4*16)) = make_uint4(0u,0u,0u,0u);
      int offp = j - i + 32;
      pos[e] = min(max(offp, 0), 64);
    }
    __syncthreads();

    // ---------- MMA over this half's chunks ----------
    int cend = h==0 ? 4 : NCHUNK;
    for (int c = h*4; c < cend; c++){
      if (c == NCHUNK-1) asm volatile("cp.async.wait_group 0;" ::: "memory");
      else               asm volatile("cp.async.wait_group 1;" ::: "memory");
      __syncthreads();                       // chunk c resident in buf c&1
      unsigned CA = smb + SM_A + (unsigned)(c - h*4)*ACH;
      unsigned CB = smb + SM_B + (unsigned)(c&1)*BCH;
      #pragma unroll
      for (int ks = 0; ks < 4; ks++){
        unsigned kb = (unsigned)ks*32;
        unsigned af[2][4];
        #pragma unroll
        for (int mt=0;mt<2;mt++){
          int r = mr0 + mt*16 + (lane & 15);
          unsigned sel = (unsigned)(lane >> 4) * 16;
          unsigned addr = CA + (unsigned)(r>>3)*1024 + SWZ((unsigned)(r&7)*128 + kb + sel);
          asm volatile("ldmatrix.sync.aligned.m8n8.x4.shared.b16 {%0,%1,%2,%3}, [%4];"
            : "=r"(af[mt][0]), "=r"(af[mt][1]), "=r"(af[mt][2]), "=r"(af[mt][3]) : "r"(addr));
        }
        unsigned bf[4][2];
        #pragma unroll
        for (int nt=0;nt<4;nt++){
          int lm = lane & 15;
          int n = nc0 + nt*8 + (lm & 7);
          unsigned sel = (unsigned)((lm >> 3) & 1) * 16;
          unsigned addr = CB + (unsigned)(n>>3)*1024 + SWZ((unsigned)(n&7)*128 + kb + sel);
          asm volatile("ldmatrix.sync.aligned.m8n8.x2.shared.b16 {%0,%1}, [%2];"
            : "=r"(bf[nt][0]), "=r"(bf[nt][1]) : "r"(addr));
        }
        #pragma unroll
        for (int mt=0;mt<2;mt++)
          #pragma unroll
          for (int nt=0;nt<4;nt++)
            asm volatile(
              "mma.sync.aligned.m16n8k16.row.col.f32.f16.f16.f32 "
              "{%0,%1,%2,%3}, {%4,%5,%6,%7}, {%8,%9}, {%0,%1,%2,%3};"
              : "+f"(acc[mt][nt][0]), "+f"(acc[mt][nt][1]),
                "+f"(acc[mt][nt][2]), "+f"(acc[mt][nt][3])
              : "r"(af[mt][0]), "r"(af[mt][1]), "r"(af[mt][2]), "r"(af[mt][3]),
                "r"(bf[nt][0]), "r"(bf[nt][1]));
      }
      __syncthreads();                       // warps done with buf c&1 (and A bufs before half switch)
      if (c+2 < NCHUNK) prefetch_chunk(smb, c+2, c&1, tid);
    }
  }

  // ---------- D -> smem C [64][CSTRIDE] (reuses A + dead B-buf0 head) ----------
  {
    float* C = (float*)(sm + SM_A);
    #pragma unroll
    for (int mt=0;mt<2;mt++)
      #pragma unroll
      for (int nt=0;nt<4;nt++){
        int row = mr0 + mt*16 + (lane >> 2);
        int col = nc0 + nt*8 + 2*(lane & 3);
        C[row*CSTRIDE + col]       = acc[mt][nt][0];
        C[row*CSTRIDE + col + 1]   = acc[mt][nt][1];
        C[(row+8)*CSTRIDE + col]   = acc[mt][nt][2];
        C[(row+8)*CSTRIDE + col+1] = acc[mt][nt][3];
      }
  }
  __syncthreads();

  // ---------- Epilogue: bias + one-hot row (fp32 exact) + LN ----------
  {
    const float* C = (const float*)(sm + SM_A);
    int row = tid >> 2, seg = tid & 3;
    const float* Wrow = We + (size_t)pos[row]*NF;
    float y[32];
    float sum = 0.f, sumsq = 0.f;
    #pragma unroll
    for (int q=0;q<32;q++){
      int f = seg*32 + q;
      float v = C[row*CSTRIDE + f] + be[f] + Wrow[f];
      y[q] = v; sum += v; sumsq += v*v;
    }
    sum   += __shfl_xor_sync(0xffffffffu, sum, 1);
    sum   += __shfl_xor_sync(0xffffffffu, sum, 2);
    sumsq += __shfl_xor_sync(0xffffffffu, sumsq, 1);
    sumsq += __shfl_xor_sync(0xffffffffu, sumsq, 2);
    float mean = sum * (1.0f/128.0f);
    float var  = sumsq * (1.0f/128.0f) - mean*mean;
    float inv  = 1.0f / sqrtf(var + 1e-5f);

    int nl2 = row >> 5, k2 = row & 31;
    float* O = out + HE_OFF + ((size_t)(g0+nl2)*Kn + k2)*NF + seg*32;
    #pragma unroll
    for (int q=0;q<32;q+=4){
      int f = seg*32 + q;
      float4 o4;
      o4.x = (y[q]   - mean)*inv*ge[f]   + betae[f];
      o4.y = (y[q+1] - mean)*inv*ge[f+1] + betae[f+1];
      o4.z = (y[q+2] - mean)*inv*ge[f+2] + betae[f+2];
      o4.w = (y[q+3] - mean)*inv*ge[f+3] + betae[f+3];
      *(float4*)(O + q) = o4;
    }
  }
}

extern "C" void kernel_launch(void* const* d_in, const int* in_sizes, int n_in,
                              void* d_out, int out_size) {
  (void)in_sizes; (void)n_in; (void)out_size;
  const float* X     = (const float*)d_in[0];
  const int*   S     = (const int*)  d_in[1];
  const float* BB    = (const float*)d_in[2];
  const float* SC    = (const float*)d_in[3];
  const int*   chain = (const int*)  d_in[4];
  const float* mask  = (const float*)d_in[5];
  const float* Wn    = (const float*)d_in[6];
  const float* bn    = (const float*)d_in[7];
  const float* gn    = (const float*)d_in[8];
  const float* betan = (const float*)d_in[9];
  const float* We    = (const float*)d_in[10];
  const float* be    = (const float*)d_in[11];
  const float* ge    = (const float*)d_in[12];
  const float* betae = (const float*)d_in[13];
  float* out = (float*)d_out;

  cudaFuncSetAttribute(edge_kernel, cudaFuncAttributeMaxDynamicSharedMemorySize, EDGE_SMEM);

  wconv_kernel<<<(NCHUNK*128*64 + 255)/256, 256>>>(We);
  pack_kernel <<<(Bn*Ln + 255)/256, 256>>>(X, mask);
  knn_kernel  <<<Bn*Ln, 256>>>(X, out);
  node_kernel <<<Bn*Ln, 128>>>(S, BB, SC, Wn, bn, gn, betan, out);
  edge_kernel <<<Bn*Ln/2, 256, EDGE_SMEM>>>(X, chain, We, be, ge, betae, out);
}

// round 16
// speedup vs baseline: 1.8721x; 1.1238x over previous
#include <cuda_runtime.h>
#include <cuda_fp16.h>
#include <math.h>

#define Bn 2
#define Ln 2048
#define Kn 32
#define NF 128

#define HV_OFF   0
#define HE_OFF   (Bn*Ln*NF)                        // 524288
#define EIDX_OFF (HE_OFF + Bn*Ln*Kn*NF)            // 17301504
#define X_OFF    (EIDX_OFF + Bn*Ln*Kn)             // 17432576

// GEMM: 128 edges (4 nodes) per block, K 403 -> 448 (7 chunks of 64 fp16)
#define NCHUNK 7
#define ACH 16384                // A chunk: 128 rows x 128B
#define BCH 16384                // B chunk: 128 rows x 128B

__device__ int g_eidx[Bn*Ln*Kn];
__device__ __align__(16) unsigned char g_Bhalf[NCHUNK*BCH];  // W fp16, SW128 chunk image
__device__ __align__(16) float4 g_ca[Bn*Ln];                 // packed (Ca.xyz, mask)

typedef unsigned long long u64;

#define SWZ(o) ((o) ^ (((o) >> 3) & 0x70))

// ---------- r11-exact math chain (div.full.f32 normalize — passing config) ----------
struct V3 { float x,y,z; };
__device__ __forceinline__ V3 vsub(V3 a, V3 b){
  V3 r; r.x=__fsub_rn(a.x,b.x); r.y=__fsub_rn(a.y,b.y); r.z=__fsub_rn(a.z,b.z); return r;
}
__device__ __forceinline__ V3 cross_x(V3 a, V3 b){
  V3 r;
  r.x = __fmaf_rn(a.y, b.z, -__fmul_rn(a.z, b.y));
  r.y = __fmaf_rn(a.z, b.x, -__fmul_rn(a.x, b.z));
  r.z = __fmaf_rn(a.x, b.y, -__fmul_rn(a.y, b.x));
  return r;
}
__device__ __forceinline__ float dot_x(V3 a, V3 b){
  return __fmaf_rn(a.z, b.z, __fmaf_rn(a.x, b.x, __fmul_rn(a.y, b.y)));
}
__device__ __forceinline__ float n2n(float x){
  if (isnan(x)) return 0.0f;
  if (isinf(x)) return copysignf(3.402823466e38f, x);
  return x;
}
__device__ __forceinline__ float div_full(float a, float b){
  float r; asm("div.full.f32 %0, %1, %2;" : "=f"(r) : "f"(a), "f"(b)); return r;
}
__device__ __forceinline__ V3 norm_x(V3 v){
  float n = __fsqrt_rn(dot_x(v,v));
  V3 r;
  r.x = n2n(div_full(v.x, n));
  r.y = n2n(div_full(v.y, n));
  r.z = n2n(div_full(v.z, n));
  return r;
}
__device__ __forceinline__ float acos_xla(float x){
  if (x == -1.0f) return 3.14159265358979323846f;
  float t = __fmaf_rn(-x, x, 1.0f);
  float s = __fsqrt_rn(t);
  return __fmul_rn(2.0f, atan2f(s, __fadd_rn(1.0f, x)));
}
__device__ __forceinline__ float dihedral(V3 p0, V3 p1, V3 p2, V3 p3){
  V3 u0=vsub(p2,p1), u1=vsub(p0,p1), u2=vsub(p3,p2);
  V3 a=norm_x(cross_x(u0,u1));
  V3 b=norm_x(cross_x(u0,u2));
  float st = dot_x(cross_x(u1,u2), u0);
  float sgn = (st>0.f)?1.f:((st<0.f)?-1.f:0.f);
  float r = __fmul_rn(sgn, acos_xla(dot_x(a,b)));
  if (isnan(r)) r = 0.f;
  return r;
}
__device__ __forceinline__ void comp_cb(const float* p, float* cb){
  float bx=p[3]-p[0], by=p[4]-p[1], bz=p[5]-p[2];
  float cx=p[6]-p[3], cy=p[7]-p[4], cz=p[8]-p[5];
  float ax = by*cz - bz*cy, ay = bz*cx - bx*cz, az = bx*cy - by*cx;
  cb[0] = -0.58273431f*ax + 0.56802827f*bx - 0.54067466f*cx + p[3];
  cb[1] = -0.58273431f*ay + 0.56802827f*by - 0.54067466f*cy + p[4];
  cb[2] = -0.58273431f*az + 0.56802827f*bz - 0.54067466f*cz + p[5];
}
__device__ __forceinline__ unsigned smem_u32(const void* p){
  unsigned a;
  asm("{ .reg .u64 t; cvta.to.shared.u64 t, %1; cvt.u32.u64 %0, t; }" : "=r"(a) : "l"(p));
  return a;
}
__device__ __forceinline__ unsigned redux_min(unsigned v){
  unsigned r; asm("redux.sync.min.u32 %0, %1, 0xffffffff;" : "=r"(r) : "r"(v)); return r;
}

// =====================================================================
// Kernel 0a: W_edge rows 65..467 -> fp16 SW128-chunk image
// =====================================================================
__global__ void wconv_kernel(const float* __restrict__ We){
  int idx = blockIdx.x*256 + threadIdx.x;           // 7*128*64 = 57344
  if (idx >= NCHUNK*128*64) return;
  int c  = idx / (128*64);
  int r  = idx % (128*64);
  int n  = r >> 6;
  int kk = r & 63;
  int kg = c*64 + kk;
  float v = (kg < 403) ? We[(65+kg)*NF + n] : 0.0f;
  unsigned off = ((unsigned)(n>>3)*1024) | ((unsigned)(n&7)*128) | (unsigned)(kk*2);
  *(__half*)(g_Bhalf + c*BCH + SWZ(off)) = __float2half_rn(v);
}

// =====================================================================
// Kernel 0b: pack (Ca.xyz, mask) for coalesced KNN loads
// =====================================================================
__global__ void pack_kernel(const float* __restrict__ X, const float* __restrict__ mask){
  int g = blockIdx.x*256 + threadIdx.x;
  if (g >= Bn*Ln) return;
  g_ca[g] = make_float4(X[(size_t)g*12+3], X[(size_t)g*12+4], X[(size_t)g*12+5], mask[g]);
}

// =====================================================================
// Kernel 1: masked distances + two-stage top-K (redux.sync extraction)
// =====================================================================
__global__ void __launch_bounds__(256) knn_kernel(
    const float* __restrict__ X, float* __restrict__ out)
{
  __shared__ float Dv[Ln];
  __shared__ float fred[8];
  __shared__ u64 wtop[8*32];

  int tid = threadIdx.x;
  int g = blockIdx.x;
  int b = g >> 11;
  int i = g & (Ln-1);
  const float4* Cb = g_ca + b*Ln;
  float4 ci = g_ca[g];
  float cax = ci.x, cay = ci.y, caz = ci.z, mi = ci.w;

  float lmax = 0.0f;
  float m2v[8];
  #pragma unroll
  for (int q=0;q<8;q++){
    int j = tid + q*256;
    float4 cj = Cb[j];
    float dx = __fsub_rn(cax, cj.x);
    float dy = __fsub_rn(cay, cj.y);
    float dz = __fsub_rn(caz, cj.z);
    float m2 = __fmul_rn(mi, cj.w);
    float ss = __fadd_rn(
        __fmaf_rn(dz, dz, __fmaf_rn(dx, dx, __fmul_rn(dy, dy))), 1e-6f);
    float D = __fmul_rn(m2, __fsqrt_rn(ss));
    Dv[j] = D; m2v[q] = m2;
    lmax = fmaxf(lmax, D);
  }
  #pragma unroll
  for (int o=16;o;o>>=1) lmax = fmaxf(lmax, __shfl_xor_sync(0xffffffffu, lmax, o));
  if ((tid&31)==0) fred[tid>>5] = lmax;
  __syncthreads();
  float Dmax = fred[0];
  #pragma unroll
  for (int q=1;q<8;q++) Dmax = fmaxf(Dmax, fred[q]);
  #pragma unroll
  for (int q=0;q<8;q++){
    int j = tid + q*256;
    Dv[j] = __fadd_rn(Dv[j],
            __fmul_rn(__fmul_rn(2.0f, __fsub_rn(1.0f, m2v[q])), Dmax));
  }
  __syncthreads();

  // Stage A: per-warp top-32 (lane owns 8 contiguous j); extraction via redux
  int w = tid >> 5, lane = tid & 31;
  u64 key[8];
  #pragma unroll
  for (int q=0;q<8;q++){
    int j = tid*8 + q;
    key[q] = ((u64)__float_as_uint(Dv[j]) << 32) | (unsigned)j;
  }
  for (int k=0;k<Kn;k++){
    u64 m = key[0];
    #pragma unroll
    for (int q=1;q<8;q++) m = (key[q] < m) ? key[q] : m;
    unsigned d32 = (unsigned)(m >> 32);
    unsigned dmin = redux_min(d32);
    unsigned cand = (d32 == dmin) ? (unsigned)m : 0xFFFFFFFFu;
    unsigned imin = redux_min(cand);
    u64 sel = ((u64)dmin << 32) | imin;
    #pragma unroll
    for (int q=0;q<8;q++) if (key[q] == sel) key[q] = ~0ull;
    if (lane==0) wtop[w*32 + k] = sel;
  }
  __syncthreads();

  // Stage B: warp 0 merges 8x32 candidates (same redux extraction)
  if (w == 0){
    u64 cnd[8];
    #pragma unroll
    for (int q=0;q<8;q++) cnd[q] = wtop[lane*8 + q];
    int base = g*Kn;
    for (int k=0;k<Kn;k++){
      u64 m = cnd[0];
      #pragma unroll
      for (int q=1;q<8;q++) m = (cnd[q] < m) ? cnd[q] : m;
      unsigned d32 = (unsigned)(m >> 32);
      unsigned dmin = redux_min(d32);
      unsigned cand = (d32 == dmin) ? (unsigned)m : 0xFFFFFFFFu;
      unsigned imin = redux_min(cand);
      u64 sel = ((u64)dmin << 32) | imin;
      #pragma unroll
      for (int q=0;q<8;q++) if (cnd[q] == sel) cnd[q] = ~0ull;
      if (lane==0){
        int bj = (int)imin;
        g_eidx[base+k] = bj;
        out[EIDX_OFF + base + k] = (float)bj;
      }
    }
  }
  if (tid < 12) out[X_OFF + (size_t)g*12 + tid] = X[(size_t)(b*Ln+i)*12 + tid];
}

// =====================================================================
// Kernel 2: node features -> row-lookup GEMM -> LN (unchanged)
// =====================================================================
__global__ void __launch_bounds__(128) node_kernel(
    const int* __restrict__ S, const float* __restrict__ BB, const float* __restrict__ SC,
    const float* __restrict__ Wn, const float* __restrict__ bn,
    const float* __restrict__ gn, const float* __restrict__ betan,
    float* __restrict__ out)
{
  __shared__ float sv[14];
  __shared__ float red1[4];
  __shared__ float red2[4];
  int g = blockIdx.x;
  int f = threadIdx.x;
  if (f < 6) sv[f] = BB[g*6 + f];
  else if (f < 14) sv[f] = SC[g*8 + (f-6)];
  __syncthreads();
  int s = S[g];
  float h = bn[f] + Wn[s*NF + f];
  #pragma unroll
  for (int j=0;j<6;j++)  h = fmaf(sv[j],   Wn[(21+j)*NF + f], h);
  #pragma unroll
  for (int j=0;j<8;j++)  h = fmaf(sv[6+j], Wn[(27+j)*NF + f], h);

  int lane = f & 31, wid = f >> 5;
  float t = h;
  #pragma unroll
  for (int o=16;o;o>>=1) t += __shfl_xor_sync(0xffffffffu, t, o);
  if (lane==0) red1[wid] = t;
  __syncthreads();
  float mean = (red1[0]+red1[1]+red1[2]+red1[3]) * (1.0f/128.0f);
  float d = h - mean;
  float t2 = d*d;
  #pragma unroll
  for (int o=16;o;o>>=1) t2 += __shfl_xor_sync(0xffffffffu, t2, o);
  if (lane==0) red2[wid] = t2;
  __syncthreads();
  float var = (red2[0]+red2[1]+red2[2]+red2[3]) * (1.0f/128.0f);
  out[HV_OFF + (size_t)g*NF + f] = d / sqrtf(var + 1e-5f) * gn[f] + betan[f];
}

// =====================================================================
// Kernel 3: edge features -> fp16 A (two 4-chunk passes) + HMMA + LN
// Block: 4 nodes = 128 edges (M=128), 256 threads, 8 warps.
// smem: misc 1KB | A: 4 x 16KB (reused per half) | B: 2 x 16KB = 97KB -> 2 CTA/SM
// Warp w: rows (w&3)*32 (2 m16 tiles), cols (w>>2)*64 (8 n8 tiles).
// =====================================================================
#define SM_X5I   64         // 4*15 floats
#define SM_POS   320        // 128 ints
#define SM_A     1024
#define SM_B     (SM_A + 4*ACH)                    // 66560
#define EDGE_SMEM (SM_B + 2*BCH)                   // 99328
#define CSTRIDE  132        // C: 128*132*4 = 67584B at SM_A (A+B buf0 region, dead)

__device__ __forceinline__ void prefetch_chunk(unsigned smb, int c, int buf, int tid){
  unsigned dst = smb + SM_B + (unsigned)buf*BCH + (unsigned)tid*16;
  const char* src = (const char*)g_Bhalf + c*BCH + tid*16;
  #pragma unroll
  for (int it=0;it<4;it++)
    asm volatile("cp.async.cg.shared.global [%0], [%1], 16;"
                 :: "r"(dst + it*4096u), "l"(src + it*4096) : "memory");
  asm volatile("cp.async.commit_group;" ::: "memory");
}

__global__ void __launch_bounds__(256, 2) edge_kernel(
    const float* __restrict__ X, const int* __restrict__ chain,
    const float* __restrict__ We, const float* __restrict__ be,
    const float* __restrict__ ge, const float* __restrict__ betae,
    float* __restrict__ out)
{
  extern __shared__ char sm[];
  unsigned smb = smem_u32(sm);
  float* x5i = (float*)(sm + SM_X5I);
  int*   pos = (int*)(sm + SM_POS);

  int tid = threadIdx.x;
  int wid = tid >> 5, lane = tid & 31;
  int g0 = blockIdx.x * 4;
  int b  = g0 >> 11;

  // prefetch first two B chunks under Phase A half 0
  prefetch_chunk(smb, 0, 0, tid);
  prefetch_chunk(smb, 1, 1, tid);

  if (tid < 48){
    int nl = tid / 12, c = tid % 12;
    x5i[nl*15 + c] = X[(size_t)(g0+nl)*12 + c];
  }
  __syncthreads();
  if (tid < 4) comp_cb(x5i + tid*15, x5i + tid*15 + 12);
  __syncthreads();

  // per-edge identity (ints only; n5 reloaded per half to cap regs)
  int e   = tid >> 1;        // edge 0..127
  int sub = tid & 1;
  int nl  = e >> 5;
  int k   = e & 31;
  int gi  = g0 + nl;
  int i   = gi & (Ln-1);
  int j   = g_eidx[gi*Kn + k];
  const float* Xb = X + (size_t)b*Ln*12;
  const float* P = x5i + nl*15;
  unsigned rowatom = (unsigned)(e>>3)*1024;
  unsigned rin     = (unsigned)(e&7)*128;

  // MMA accumulators
  int mr0 = (wid & 3) * 32;
  int nc0 = (wid >> 2) * 64;
  float acc[2][8][4];
  #pragma unroll
  for (int mt=0;mt<2;mt++)
    #pragma unroll
    for (int nt=0;nt<8;nt++)
      #pragma unroll
      for (int q=0;q<4;q++) acc[mt][nt][q] = 0.f;

  #pragma unroll
  for (int h=0; h<2; h++){
    // ---------- Phase A half h: features -> A bufs 0..3 ----------
    {
      float n5[15];
      #pragma unroll
      for (int c=0;c<12;c++) n5[c] = Xb[(size_t)j*12 + c];
      comp_cb(n5, n5+12);

      int pstart = h==0 ? sub : 16+sub;
      int pend   = h==0 ? 16 : 25;
      for (int p = pstart; p < pend; p += 2){
        int a = p/5, q = p%5;
        float dx = P[a*3+0]-n5[q*3+0];
        float dy = P[a*3+1]-n5[q*3+1];
        float dz = P[a*3+2]-n5[q*3+2];
        float d = sqrtf(dx*dx + dy*dy + dz*dz + 1e-6f);
        unsigned h2[8];
        #pragma unroll
        for (int r2=0;r2<8;r2++){
          float mu0 = (float)(2*r2)   * (20.0f/15.0f);
          float mu1 = (float)(2*r2+1) * (20.0f/15.0f);
          float t0 = (d - mu0) * 0.8f;
          float t1 = (d - mu1) * 0.8f;
          __half2 hh = __floats2half2_rn(__expf(-t0*t0), __expf(-t1*t1));
          h2[r2] = *(unsigned*)&hh;
        }
        int cb2 = (p >> 2) - h*4;
        unsigned kb = (unsigned)(p&3)*32;
        char* base = sm + SM_A + cb2*ACH + rowatom;
        *(uint4*)(base + SWZ(rin + kb))      = make_uint4(h2[0],h2[1],h2[2],h2[3]);
        *(uint4*)(base + SWZ(rin + kb + 16)) = make_uint4(h2[4],h2[5],h2[6],h2[7]);
      }
      if (h==1 && sub == 1){
        float et = (chain[b*Ln + j] == chain[gi]) ? 2.0f : 1.0f;
        V3 Ni  = {P[0],P[1],P[2]},  Cai = {P[3],P[4],P[5]},  Ci = {P[6],P[7],P[8]};
        V3 Nj  = {n5[0],n5[1],n5[2]}, Caj = {n5[3],n5[4],n5[5]}, Cj = {n5[6],n5[7],n5[8]};
        float d0 = dihedral(Ci, Nj, Caj, Cj);
        float d1 = dihedral(Ni, Cai, Ci, Nj);
        __half2 hh0 = __floats2half2_rn(et, d0);
        __half2 hh1 = __floats2half2_rn(d1, 0.f);
        char* base = sm + SM_A + 2*ACH + rowatom;      // chunk 6 -> buf 2
        *(uint4*)(base + SWZ(rin + 32)) = make_uint4(*(unsigned*)&hh0, *(unsigned*)&hh1, 0u, 0u);
        #pragma unroll
        for (int s4=1;s4<6;s4++)
          *(uint4*)(base + SWZ(rin + 32 + (unsigned)s4*16)) = make_uint4(0u,0u,0u,0u);
        int offp = j - i + 32;
        pos[e] = min(max(offp, 0), 64);
      }
    }
    __syncthreads();

    // ---------- MMA over this half's chunks ----------
    int cend = h==0 ? 4 : NCHUNK;
    for (int c = h*4; c < cend; c++){
      if (c == NCHUNK-1) asm volatile("cp.async.wait_group 0;" ::: "memory");
      else               asm volatile("cp.async.wait_group 1;" ::: "memory");
      __syncthreads();                       // chunk c resident in buf c&1
      unsigned CA = smb + SM_A + (unsigned)(c - h*4)*ACH;
      unsigned CB = smb + SM_B + (unsigned)(c&1)*BCH;
      #pragma unroll
      for (int ks = 0; ks < 4; ks++){
        unsigned kb = (unsigned)ks*32;
        unsigned af[2][4];
        #pragma unroll
        for (int mt=0;mt<2;mt++){
          int r = mr0 + mt*16 + (lane & 15);
          unsigned sel = (unsigned)(lane >> 4) * 16;
          unsigned addr = CA + (unsigned)(r>>3)*1024 + SWZ((unsigned)(r&7)*128 + kb + sel);
          asm volatile("ldmatrix.sync.aligned.m8n8.x4.shared.b16 {%0,%1,%2,%3}, [%4];"
            : "=r"(af[mt][0]), "=r"(af[mt][1]), "=r"(af[mt][2]), "=r"(af[mt][3]) : "r"(addr));
        }
        unsigned bf[8][2];
        #pragma unroll
        for (int ntp=0;ntp<4;ntp++){
          // x4: matrices = (cols+0..7, k0-7), (cols+0..7, k8-15), (cols+8..15, k0-7), (cols+8..15, k8-15)
          int col = nc0 + ntp*16 + ((lane >> 4) << 3) + (lane & 7);
          unsigned khalf = (unsigned)((lane >> 3) & 1) * 16;
          unsigned addr = CB + (unsigned)(col>>3)*1024 + SWZ((unsigned)(col&7)*128 + kb + khalf);
          asm volatile("ldmatrix.sync.aligned.m8n8.x4.shared.b16 {%0,%1,%2,%3}, [%4];"
            : "=r"(bf[2*ntp][0]), "=r"(bf[2*ntp][1]), "=r"(bf[2*ntp+1][0]), "=r"(bf[2*ntp+1][1])
            : "r"(addr));
        }
        #pragma unroll
        for (int mt=0;mt<2;mt++)
          #pragma unroll
          for (int nt=0;nt<8;nt++)
            asm volatile(
              "mma.sync.aligned.m16n8k16.row.col.f32.f16.f16.f32 "
              "{%0,%1,%2,%3}, {%4,%5,%6,%7}, {%8,%9}, {%0,%1,%2,%3};"
              : "+f"(acc[mt][nt][0]), "+f"(acc[mt][nt][1]),
                "+f"(acc[mt][nt][2]), "+f"(acc[mt][nt][3])
              : "r"(af[mt][0]), "r"(af[mt][1]), "r"(af[mt][2]), "r"(af[mt][3]),
                "r"(bf[nt][0]), "r"(bf[nt][1]));
      }
      __syncthreads();                       // warps done with buf c&1 / A bufs
      if (c+2 < NCHUNK) prefetch_chunk(smb, c+2, c&1, tid);
    }
  }

  // ---------- D -> smem C [128][CSTRIDE] ----------
  {
    float* C = (float*)(sm + SM_A);
    #pragma unroll
    for (int mt=0;mt<2;mt++)
      #pragma unroll
      for (int nt=0;nt<8;nt++){
        int row = mr0 + mt*16 + (lane >> 2);
        int col = nc0 + nt*8 + 2*(lane & 3);
        C[row*CSTRIDE + col]       = acc[mt][nt][0];
        C[row*CSTRIDE + col + 1]   = acc[mt][nt][1];
        C[(row+8)*CSTRIDE + col]   = acc[mt][nt][2];
        C[(row+8)*CSTRIDE + col+1] = acc[mt][nt][3];
      }
  }
  __syncthreads();

  // ---------- Epilogue: bias + one-hot row (fp32 exact) + LN (two-pass) ----------
  {
    const float* C = (const float*)(sm + SM_A);
    int row = tid >> 1, seg = tid & 1;      // 2 threads/row, 64 feats each
    const float* Wrow = We + (size_t)pos[row]*NF;
    float sum = 0.f, sumsq = 0.f;
    #pragma unroll
    for (int q=0;q<64;q++){
      int f = seg*64 + q;
      float v = C[row*CSTRIDE + f] + be[f] + Wrow[f];
      sum += v; sumsq += v*v;
    }
    sum   += __shfl_xor_sync(0xffffffffu, sum, 1);
    sumsq += __shfl_xor_sync(0xffffffffu, sumsq, 1);
    float mean = sum * (1.0f/128.0f);
    float var  = sumsq * (1.0f/128.0f) - mean*mean;
    float inv  = 1.0f / sqrtf(var + 1e-5f);

    int nl2 = row >> 5, k2 = row & 31;
    float* O = out + HE_OFF + ((size_t)(g0+nl2)*Kn + k2)*NF + seg*64;
    #pragma unroll
    for (int q=0;q<64;q+=4){
      int f = seg*64 + q;
      float4 o4;
      o4.x = (C[row*CSTRIDE+f]   + be[f]   + Wrow[f]   - mean)*inv*ge[f]   + betae[f];
      o4.y = (C[row*CSTRIDE+f+1] + be[f+1] + Wrow[f+1] - mean)*inv*ge[f+1] + betae[f+1];
      o4.z = (C[row*CSTRIDE+f+2] + be[f+2] + Wrow[f+2] - mean)*inv*ge[f+2] + betae[f+2];
      o4.w = (C[row*CSTRIDE+f+3] + be[f+3] + Wrow[f+3] - mean)*inv*ge[f+3] + betae[f+3];
      *(float4*)(O + q) = o4;
    }
  }
}

extern "C" void kernel_launch(void* const* d_in, const int* in_sizes, int n_in,
                              void* d_out, int out_size) {
  (void)in_sizes; (void)n_in; (void)out_size;
  const float* X     = (const float*)d_in[0];
  const int*   S     = (const int*)  d_in[1];
  const float* BB    = (const float*)d_in[2];
  const float* SC    = (const float*)d_in[3];
  const int*   chain = (const int*)  d_in[4];
  const float* mask  = (const float*)d_in[5];
  const float* Wn    = (const float*)d_in[6];
  const float* bn    = (const float*)d_in[7];
  const float* gn    = (const float*)d_in[8];
  const float* betan = (const float*)d_in[9];
  const float* We    = (const float*)d_in[10];
  const float* be    = (const float*)d_in[11];
  const float* ge    = (const float*)d_in[12];
  const float* betae = (const float*)d_in[13];
  float* out = (float*)d_out;

  cudaFuncSetAttribute(edge_kernel, cudaFuncAttributeMaxDynamicSharedMemorySize, EDGE_SMEM);

  wconv_kernel<<<(NCHUNK*128*64 + 255)/256, 256>>>(We);
  pack_kernel <<<(Bn*Ln + 255)/256, 256>>>(X, mask);
  knn_kernel  <<<Bn*Ln, 256>>>(X, out);
  node_kernel <<<Bn*Ln, 128>>>(S, BB, SC, Wn, bn, gn, betan, out);
  edge_kernel <<<Bn*Ln/4, 256, EDGE_SMEM>>>(X, chain, We, be, ge, betae, out);
}